// round 12
// baseline (speedup 1.0000x reference)
#include <cuda_runtime.h>
#include <cuda_fp16.h>
#include <math.h>
#include <stdint.h>

// Problem constants
#define Bv   4
#define Sv   2048
#define Dv   512
#define Hv   8
#define Ev   4
#define HDv  64
#define Mv   (Bv * Sv)     // 8192
#define DEv  (Dv * Ev)     // 2048
#define QKVN (3 * Dv)      // 1536

// Scratch (device globals; no allocation allowed)
__device__ __half g_xh   [Mv * Dv];
__device__ __half g_wqkvT[QKVN * Dv];   // [Wq*s|Wk*s|Wv]^T : [N][K]
__device__ __half g_woT  [Dv * Dv];
__device__ __half g_w1T  [DEv * Dv];
__device__ __half g_w2T  [Dv * DEv];
__device__ __half g_qk   [Mv * 1024];   // q|k halves, row stride 1024
__device__ __half g_vt   [Dv * Mv];     // v transposed: [(h*64+d)][b*2048+s]
__device__ __half g_oh   [Mv * Dv];
__device__ __half g_x1h  [Mv * Dv];
__device__ __half g_hh   [Mv * DEv];
__device__ float  g_x1res[Mv * Dv];

enum { EP_QKV = 0, EP_RES = 1, EP_BIAS_GELU = 2, EP_BIAS_RES = 3 };

__device__ __forceinline__ float gelu_tanh(float x) {
    float x3 = x * x * x;
    float t = tanhf(0.7978845608028654f * (x + 0.044715f * x3));
    return 0.5f * x * (1.0f + t);
}

__device__ __forceinline__ uint32_t smem_u32(const void* p) {
    uint32_t a;
    asm("{ .reg .u64 t; cvta.to.shared.u64 t, %1; cvt.u32.u64 %0, t; }"
        : "=r"(a) : "l"(p));
    return a;
}

#define CP_ASYNC16(dst, src) \
    asm volatile("cp.async.cg.shared.global [%0], [%1], 16;" :: "r"(dst), "l"(src))
#define CP_COMMIT() asm volatile("cp.async.commit_group;" ::: "memory")
#define CP_WAIT(n)  asm volatile("cp.async.wait_group %0;" :: "n"(n) : "memory")

#define LDSM_X4(r0, r1, r2, r3, a) \
    asm volatile("ldmatrix.sync.aligned.m8n8.x4.shared.b16 {%0,%1,%2,%3}, [%4];" \
        : "=r"(r0), "=r"(r1), "=r"(r2), "=r"(r3) : "r"(a))

__device__ __forceinline__ void mma_f16(float c[4], uint32_t a0, uint32_t a1,
                                        uint32_t a2, uint32_t a3,
                                        uint32_t b0, uint32_t b1) {
    asm volatile(
        "mma.sync.aligned.m16n8k16.row.col.f32.f16.f16.f32 "
        "{%0,%1,%2,%3}, {%4,%5,%6,%7}, {%8,%9}, {%0,%1,%2,%3};"
        : "+f"(c[0]), "+f"(c[1]), "+f"(c[2]), "+f"(c[3])
        : "r"(a0), "r"(a1), "r"(a2), "r"(a3), "r"(b0), "r"(b1));
}

// ---------------------------------------------------------------------------
// Fused preprocessing (one launch): 6 weight transposes + x convert.
// scale passed for Wq/Wk includes sqrt(log2(e)) so scores land in log2 domain.
// ---------------------------------------------------------------------------
__device__ __forceinline__ void transpose_tile(
    const float* __restrict__ src, __half* __restrict__ dst,
    int R, int C, float scale, int bx, int by)
{
    __shared__ float t[32][33];
    const int tx = threadIdx.x, ty = threadIdx.y;
#pragma unroll
    for (int j = 0; j < 4; j++)
        t[ty + 8 * j][tx] = src[(size_t)(by * 32 + ty + 8 * j) * C + bx * 32 + tx];
    __syncthreads();
#pragma unroll
    for (int j = 0; j < 4; j++)
        dst[(size_t)(bx * 32 + ty + 8 * j) * R + by * 32 + tx] =
            __float2half_rn(t[tx][ty + 8 * j] * scale);
}

__global__ __launch_bounds__(256)
void prep_all(const float* __restrict__ x,  const float* __restrict__ Wq,
              const float* __restrict__ Wk, const float* __restrict__ Wv,
              const float* __restrict__ Wo, const float* __restrict__ W1,
              const float* __restrict__ W2, float scale)
{
    const int gb = blockIdx.x;
    if (gb < 256) {
        transpose_tile(Wq, g_wqkvT,             Dv, Dv, scale, gb & 15, gb >> 4);
    } else if (gb < 512) {
        int t = gb - 256;
        transpose_tile(Wk, g_wqkvT + 512 * Dv,  Dv, Dv, scale, t & 15, t >> 4);
    } else if (gb < 768) {
        int t = gb - 512;
        transpose_tile(Wv, g_wqkvT + 1024 * Dv, Dv, Dv, 1.0f, t & 15, t >> 4);
    } else if (gb < 1024) {
        int t = gb - 768;
        transpose_tile(Wo, g_woT, Dv, Dv, 1.0f, t & 15, t >> 4);
    } else if (gb < 2048) {
        int t = gb - 1024;                      // W1: R=512, C=2048, grid 64x16
        transpose_tile(W1, g_w1T, Dv, DEv, 1.0f, t & 63, t >> 6);
    } else if (gb < 3072) {
        int t = gb - 2048;                      // W2: R=2048, C=512, grid 16x64
        transpose_tile(W2, g_w2T, DEv, Dv, 1.0f, t & 15, t >> 4);
    } else {
        int t = gb - 3072;
        int tid = threadIdx.y * 32 + threadIdx.x;
        int i = t * 256 + tid;
        for (int idx = i; idx < Mv * Dv / 2; idx += 256 * 256) {
            float2 v = *(const float2*)(x + 2 * idx);
            *(__half2*)(g_xh + 2 * idx) = __floats2half2_rn(v.x, v.y);
        }
    }
}

// ---------------------------------------------------------------------------
// fp16 GEMM: 5-stage cp.async ring (4 groups in flight), ldmatrix, m16n8k16.
// Unchanged from round 11.
// ---------------------------------------------------------------------------
#define HS 40
#define STG_HALFS (2 * 128 * HS)                 // 10240
#define GEMM_SMEM (5 * STG_HALFS * 2)            // 102400 B

template <int EPI>
__global__ __launch_bounds__(256, 2)
void gemm_mma(const __half* __restrict__ A, const __half* __restrict__ BT,
              const float* __restrict__ bias, const float* __restrict__ res,
              float* __restrict__ Cf, __half* __restrict__ Ch,
              __half* __restrict__ Vt, int M, int N, int K)
{
    extern __shared__ __half smh[];

    const int tid = threadIdx.x;
    const int wid = tid >> 5;
    const int lid = tid & 31;
    const int gid = lid >> 2;
    const int tq  = lid & 3;
    const int wm  = (wid >> 1) * 32;
    const int wn  = (wid & 1) * 64;
    const int bm  = blockIdx.y * 128;
    const int bn  = blockIdx.x * 128;
    const int NS  = K >> 5;

    const int lrow = (lid & 7) + ((lid >> 3) & 1) * 8;
    const int ak16 = lid >> 4;
    const int brow = lid & 7;
    const int bk16 = (lid >> 3) & 1;
    const int bn8  = (lid >> 4) & 1;

    auto issue = [&](int s, int buf) {
        __half* ab = smh + buf * STG_HALFS;
        __half* bb = ab + 128 * HS;
        const __half* Ap = A  + (size_t)bm * K + s * 32;
        const __half* Bp = BT + (size_t)bn * K + s * 32;
#pragma unroll
        for (int it = 0; it < 2; it++) {
            int idx = it * 256 + tid;
            int r = idx >> 2, c = (idx & 3) * 8;
            CP_ASYNC16(smem_u32(ab + r * HS + c), Ap + (size_t)r * K + c);
        }
#pragma unroll
        for (int it = 0; it < 2; it++) {
            int idx = it * 256 + tid;
            int r = idx >> 2, c = (idx & 3) * 8;
            CP_ASYNC16(smem_u32(bb + r * HS + c), Bp + (size_t)r * K + c);
        }
        CP_COMMIT();
    };

    float acc[2][8][4];
#pragma unroll
    for (int mt = 0; mt < 2; mt++)
#pragma unroll
        for (int nt = 0; nt < 8; nt++)
#pragma unroll
            for (int u = 0; u < 4; u++) acc[mt][nt][u] = 0.0f;

    issue(0, 0); issue(1, 1); issue(2, 2); issue(3, 3);

    for (int s = 0; s < NS; s++) {
        const int rem = NS - 1 - s;
        if (rem >= 3)      { CP_WAIT(3); }
        else if (rem == 2) { CP_WAIT(2); }
        else if (rem == 1) { CP_WAIT(1); }
        else               { CP_WAIT(0); }
        __syncthreads();
        if (s + 4 < NS) issue(s + 4, (s + 4) % 5);

        const uint32_t stage = smem_u32(smh + (s % 5) * STG_HALFS);
        const uint32_t a_base = stage + ((wm + lrow) * HS) * 2 + ak16 * 16;
        const uint32_t b_base = stage + 128 * HS * 2
                              + ((wn + bn8 * 8 + brow) * HS) * 2 + bk16 * 16;
#pragma unroll
        for (int ks = 0; ks < 2; ks++) {
            uint32_t a[2][4];
#pragma unroll
            for (int mt = 0; mt < 2; mt++)
                LDSM_X4(a[mt][0], a[mt][1], a[mt][2], a[mt][3],
                        a_base + mt * (16 * HS * 2) + ks * 32);
#pragma unroll
            for (int p = 0; p < 4; p++) {
                uint32_t b0, b1, b2, b3;
                LDSM_X4(b0, b1, b2, b3, b_base + p * (16 * HS * 2) + ks * 32);
#pragma unroll
                for (int mt = 0; mt < 2; mt++) {
                    mma_f16(acc[mt][2 * p],     a[mt][0], a[mt][1], a[mt][2], a[mt][3], b0, b1);
                    mma_f16(acc[mt][2 * p + 1], a[mt][0], a[mt][1], a[mt][2], a[mt][3], b2, b3);
                }
            }
        }
    }

    // Epilogue
#pragma unroll
    for (int mt = 0; mt < 2; mt++) {
#pragma unroll
        for (int half_ = 0; half_ < 2; half_++) {
            const int row = bm + wm + mt * 16 + gid + half_ * 8;
#pragma unroll
            for (int nt = 0; nt < 8; nt++) {
                const int col = bn + wn + nt * 8 + 2 * tq;
                float v0 = acc[mt][nt][half_ * 2 + 0];
                float v1 = acc[mt][nt][half_ * 2 + 1];
                if (EPI == EP_QKV) {
                    if (bn < 1024) {
                        *(__half2*)(Ch + (size_t)row * 1024 + col) =
                            __floats2half2_rn(v0, v1);
                    } else {
                        Vt[(size_t)(col - 1024) * Mv + row] = __float2half_rn(v0);
                        Vt[(size_t)(col - 1023) * Mv + row] = __float2half_rn(v1);
                    }
                } else if (EPI == EP_RES) {
                    v0 += res[(size_t)row * N + col];
                    v1 += res[(size_t)row * N + col + 1];
                    *(float2*)(Cf + (size_t)row * N + col) = make_float2(v0, v1);
                    *(__half2*)(Ch + (size_t)row * N + col) = __floats2half2_rn(v0, v1);
                } else if (EPI == EP_BIAS_GELU) {
                    v0 = gelu_tanh(v0 + bias[col]);
                    v1 = gelu_tanh(v1 + bias[col + 1]);
                    *(__half2*)(Ch + (size_t)row * N + col) = __floats2half2_rn(v0, v1);
                } else {   // EP_BIAS_RES
                    v0 += bias[col]     + res[(size_t)row * N + col];
                    v1 += bias[col + 1] + res[(size_t)row * N + col + 1];
                    *(float2*)(Cf + (size_t)row * N + col) = make_float2(v0, v1);
                }
            }
        }
    }
}

// ---------------------------------------------------------------------------
// fp16 flash attention: 256 q-rows/CTA, 512 threads (16 warps), 1 CTA/SM.
// 4-stage cp.async K+V ring (3 tiles in flight). Scores in log2 domain
// (scale folded at prep) -> exp2f softmax.
// SMEM (halfs): ring 4 x 9216 = 36864; Qs/Ps region at 36864 (18432 halfs).
// Total 55296 halfs = 110592 B -> 1 CTA/SM.
// ---------------------------------------------------------------------------
#define ATTN_SMEM (55296 * 2)   // 110592 B
#define NT_TILES (Sv / 64)      // 32

__global__ __launch_bounds__(512, 1)
void attn_mma(const __half* __restrict__ qk, const __half* __restrict__ vt,
              __half* __restrict__ o)
{
    extern __shared__ __half smh[];
    __half* Ps = smh + 36864;
    __half* Qs = smh + 36864;   // overlap: Q staged before Ps first used

    const int tid = threadIdx.x;
    const int wid = tid >> 5;       // 0..15
    const int lid = tid & 31;
    const int gid = lid >> 2;
    const int tq  = lid & 3;
    const int qt  = blockIdx.x;     // 0..7 (256-row tiles)
    const int h   = blockIdx.y;
    const int b   = blockIdx.z;

    const int lrow = (lid & 7) + ((lid >> 3) & 1) * 8;
    const int ak16 = lid >> 4;
    const int brow = lid & 7;
    const int bk16 = (lid >> 3) & 1;
    const int bn8  = (lid >> 4) & 1;

    const __half* qb  = qk + ((size_t)b * Sv + qt * 256) * 1024 + h * HDv;
    const __half* kb  = qk + (size_t)b * Sv * 1024 + 512 + h * HDv;
    const __half* vtb = vt + (size_t)(h * HDv) * Mv + b * Sv;

    auto issue_tile = [&](int kt, int buf) {
        // 512 threads: each does 1 K chunk + 1 V chunk (8 halfs each)
        {
            int key = tid >> 3, ch = (tid & 7) * 8;
            CP_ASYNC16(smem_u32(smh + buf * 9216 + key * 72 + ch),
                       kb + (size_t)(kt * 64 + key) * 1024 + ch);
            CP_ASYNC16(smem_u32(smh + buf * 9216 + 4608 + key * 72 + ch),
                       vtb + (size_t)key * Mv + kt * 64 + ch);
        }
        CP_COMMIT();
    };

    issue_tile(0, 0);

    // Stage Q [256][72] via cp.async (own group): 2048 chunks, 4 per thread
#pragma unroll
    for (int it = 0; it < 4; it++) {
        int idx = it * 512 + tid;
        int r = idx >> 3, c = (idx & 7) * 8;
        CP_ASYNC16(smem_u32(Qs + r * 72 + c), qb + (size_t)r * 1024 + c);
    }
    CP_COMMIT();
    issue_tile(1, 1);
    issue_tile(2, 2);

    CP_WAIT(2);          // tile0 + Q complete; tiles 1,2 in flight
    __syncthreads();

    uint32_t qf[4][4];
    {
        const uint32_t qaddr = smem_u32(Qs) + ((wid * 16 + lrow) * 72) * 2 + ak16 * 16;
#pragma unroll
        for (int ks = 0; ks < 4; ks++)
            LDSM_X4(qf[ks][0], qf[ks][1], qf[ks][2], qf[ks][3], qaddr + ks * 32);
    }
    __syncthreads();   // Qs region becomes Ps after this point

    float oacc[8][4];
#pragma unroll
    for (int dt = 0; dt < 8; dt++)
#pragma unroll
        for (int u = 0; u < 4; u++) oacc[dt][u] = 0.0f;
    float mrow0 = -1e30f, mrow1 = -1e30f, lrow0 = 0.0f, lrow1 = 0.0f;
    __half* Pw = Ps + wid * 16 * 72;
    const uint32_t paddr = smem_u32(Pw) + (lrow * 72) * 2 + ak16 * 16;

    for (int kt = 0; kt < NT_TILES; kt++) {
        const int buf = kt & 3;
        const int rem = NT_TILES - 1 - kt;
        if (rem >= 2)      { CP_WAIT(2); }
        else if (rem == 1) { CP_WAIT(1); }
        else               { CP_WAIT(0); }
        __syncthreads();
        if (kt + 3 < NT_TILES) issue_tile(kt + 3, (kt + 3) & 3);

        const uint32_t kaddr = smem_u32(smh + buf * 9216)
                             + ((bn8 * 8 + brow) * 72) * 2 + bk16 * 16;
        const uint32_t vaddr = smem_u32(smh + buf * 9216 + 4608)
                             + ((bn8 * 8 + brow) * 72) * 2 + bk16 * 16;

        // ---- S = Q @ K^T (scores already in log2 domain) ----
        float sacc[8][4];
#pragma unroll
        for (int nt = 0; nt < 8; nt++)
#pragma unroll
            for (int u = 0; u < 4; u++) sacc[nt][u] = 0.0f;
#pragma unroll
        for (int ks = 0; ks < 4; ks++) {
#pragma unroll
            for (int p = 0; p < 4; p++) {
                uint32_t b0, b1, b2, b3;
                LDSM_X4(b0, b1, b2, b3, kaddr + p * (16 * 72 * 2) + ks * 32);
                mma_f16(sacc[2 * p],     qf[ks][0], qf[ks][1], qf[ks][2], qf[ks][3], b0, b1);
                mma_f16(sacc[2 * p + 1], qf[ks][0], qf[ks][1], qf[ks][2], qf[ks][3], b2, b3);
            }
        }

        // ---- online softmax (exp2 domain) ----
        float mx0 = -1e30f, mx1 = -1e30f;
#pragma unroll
        for (int nt = 0; nt < 8; nt++) {
            mx0 = fmaxf(mx0, fmaxf(sacc[nt][0], sacc[nt][1]));
            mx1 = fmaxf(mx1, fmaxf(sacc[nt][2], sacc[nt][3]));
        }
        mx0 = fmaxf(mx0, __shfl_xor_sync(0xffffffffu, mx0, 1));
        mx0 = fmaxf(mx0, __shfl_xor_sync(0xffffffffu, mx0, 2));
        mx1 = fmaxf(mx1, __shfl_xor_sync(0xffffffffu, mx1, 1));
        mx1 = fmaxf(mx1, __shfl_xor_sync(0xffffffffu, mx1, 2));
        float mn0 = fmaxf(mrow0, mx0), mn1 = fmaxf(mrow1, mx1);
        float corr0 = exp2f(mrow0 - mn0), corr1 = exp2f(mrow1 - mn1);
        float ps0 = 0.0f, ps1 = 0.0f;
#pragma unroll
        for (int nt = 0; nt < 8; nt++) {
            sacc[nt][0] = exp2f(sacc[nt][0] - mn0);
            sacc[nt][1] = exp2f(sacc[nt][1] - mn0);
            sacc[nt][2] = exp2f(sacc[nt][2] - mn1);
            sacc[nt][3] = exp2f(sacc[nt][3] - mn1);
            ps0 += sacc[nt][0] + sacc[nt][1];
            ps1 += sacc[nt][2] + sacc[nt][3];
        }
        ps0 += __shfl_xor_sync(0xffffffffu, ps0, 1);
        ps0 += __shfl_xor_sync(0xffffffffu, ps0, 2);
        ps1 += __shfl_xor_sync(0xffffffffu, ps1, 1);
        ps1 += __shfl_xor_sync(0xffffffffu, ps1, 2);
        lrow0 = lrow0 * corr0 + ps0;
        lrow1 = lrow1 * corr1 + ps1;
        mrow0 = mn0; mrow1 = mn1;
#pragma unroll
        for (int dt = 0; dt < 8; dt++) {
            oacc[dt][0] *= corr0; oacc[dt][1] *= corr0;
            oacc[dt][2] *= corr1; oacc[dt][3] *= corr1;
        }

        // ---- P -> per-warp SMEM (half) ----
#pragma unroll
        for (int nt = 0; nt < 8; nt++) {
            *(__half2*)&Pw[gid       * 72 + nt * 8 + 2 * tq] =
                __floats2half2_rn(sacc[nt][0], sacc[nt][1]);
            *(__half2*)&Pw[(gid + 8) * 72 + nt * 8 + 2 * tq] =
                __floats2half2_rn(sacc[nt][2], sacc[nt][3]);
        }
        __syncwarp();

        // ---- O += P @ V ----
#pragma unroll
        for (int ks = 0; ks < 4; ks++) {
            uint32_t pa0, pa1, pa2, pa3;
            LDSM_X4(pa0, pa1, pa2, pa3, paddr + ks * 32);
#pragma unroll
            for (int p = 0; p < 4; p++) {
                uint32_t b0, b1, b2, b3;
                LDSM_X4(b0, b1, b2, b3, vaddr + p * (16 * 72 * 2) + ks * 32);
                mma_f16(oacc[2 * p],     pa0, pa1, pa2, pa3, b0, b1);
                mma_f16(oacc[2 * p + 1], pa0, pa1, pa2, pa3, b2, b3);
            }
        }
        __syncwarp();
    }

    // ---- normalize, write O (half) ----
    float inv0 = 1.0f / lrow0, inv1 = 1.0f / lrow1;
    __half* ob = o + ((size_t)b * Sv + qt * 256 + wid * 16) * Dv + h * HDv;
#pragma unroll
    for (int dt = 0; dt < 8; dt++) {
        int col = dt * 8 + 2 * tq;
        *(__half2*)(ob + (size_t)gid * Dv + col) =
            __floats2half2_rn(oacc[dt][0] * inv0, oacc[dt][1] * inv0);
        *(__half2*)(ob + (size_t)(gid + 8) * Dv + col) =
            __floats2half2_rn(oacc[dt][2] * inv1, oacc[dt][3] * inv1);
    }
}

// ---------------------------------------------------------------------------
// Launch
// ---------------------------------------------------------------------------
extern "C" void kernel_launch(void* const* d_in, const int* in_sizes, int n_in,
                              void* d_out, int out_size)
{
    const float* x  = (const float*)d_in[0];
    const float* Wq = (const float*)d_in[1];
    const float* Wk = (const float*)d_in[2];
    const float* Wv = (const float*)d_in[3];
    const float* Wo = (const float*)d_in[4];
    const float* W1 = (const float*)d_in[5];
    const float* b1 = (const float*)d_in[6];
    const float* W2 = (const float*)d_in[7];
    const float* b2 = (const float*)d_in[8];
    float* out = (float*)d_out;

    __half *xh, *wqkvT, *woT, *w1T, *w2T, *qk, *vt, *oh, *x1h, *hh;
    float* x1res;
    cudaGetSymbolAddress((void**)&xh,    g_xh);
    cudaGetSymbolAddress((void**)&wqkvT, g_wqkvT);
    cudaGetSymbolAddress((void**)&woT,   g_woT);
    cudaGetSymbolAddress((void**)&w1T,   g_w1T);
    cudaGetSymbolAddress((void**)&w2T,   g_w2T);
    cudaGetSymbolAddress((void**)&qk,    g_qk);
    cudaGetSymbolAddress((void**)&vt,    g_vt);
    cudaGetSymbolAddress((void**)&oh,    g_oh);
    cudaGetSymbolAddress((void**)&x1h,   g_x1h);
    cudaGetSymbolAddress((void**)&hh,    g_hh);
    cudaGetSymbolAddress((void**)&x1res, g_x1res);

    cudaFuncSetAttribute(gemm_mma<EP_QKV>,       cudaFuncAttributeMaxDynamicSharedMemorySize, GEMM_SMEM);
    cudaFuncSetAttribute(gemm_mma<EP_RES>,       cudaFuncAttributeMaxDynamicSharedMemorySize, GEMM_SMEM);
    cudaFuncSetAttribute(gemm_mma<EP_BIAS_GELU>, cudaFuncAttributeMaxDynamicSharedMemorySize, GEMM_SMEM);
    cudaFuncSetAttribute(gemm_mma<EP_BIAS_RES>,  cudaFuncAttributeMaxDynamicSharedMemorySize, GEMM_SMEM);
    cudaFuncSetAttribute(attn_mma, cudaFuncAttributeMaxDynamicSharedMemorySize, ATTN_SMEM);

    // 512^(-0.25) * sqrt(log2(e)) -> scores come out of QK^T in log2 domain
    const float scale = 0.21022410381342865f * 1.2011224087864498f;
    dim3 blk(256);

    prep_all<<<3328, dim3(32, 8)>>>(x, Wq, Wk, Wv, Wo, W1, W2, scale);

    // qkv projections: q|k -> g_qk, v -> g_vt (transposed)
    gemm_mma<EP_QKV><<<dim3(QKVN / 128, Mv / 128), blk, GEMM_SMEM>>>(
        xh, wqkvT, nullptr, nullptr, nullptr, qk, vt, Mv, QKVN, Dv);

    attn_mma<<<dim3(Sv / 256, Hv, Bv), dim3(512), ATTN_SMEM>>>(qk, vt, oh);

    // x1 = o @ Wo + x   (fp32 res + half copy)
    gemm_mma<EP_RES><<<dim3(Dv / 128, Mv / 128), blk, GEMM_SMEM>>>(
        oh, woT, nullptr, x, x1res, x1h, nullptr, Mv, Dv, Dv);
    // h = gelu(x1 @ W1 + b1)
    gemm_mma<EP_BIAS_GELU><<<dim3(DEv / 128, Mv / 128), blk, GEMM_SMEM>>>(
        x1h, w1T, b1, nullptr, nullptr, hh, nullptr, Mv, DEv, Dv);
    // out = h @ W2 + b2 + x1
    gemm_mma<EP_BIAS_RES><<<dim3(Dv / 128, Mv / 128), blk, GEMM_SMEM>>>(
        hh, w2T, b2, x1res, out, nullptr, nullptr, Mv, Dv, DEv);
}

// round 13
// speedup vs baseline: 1.0230x; 1.0230x over previous
#include <cuda_runtime.h>
#include <cuda_fp16.h>
#include <math.h>
#include <stdint.h>

// Problem constants
#define Bv   4
#define Sv   2048
#define Dv   512
#define Hv   8
#define Ev   4
#define HDv  64
#define Mv   (Bv * Sv)     // 8192
#define DEv  (Dv * Ev)     // 2048
#define QKVN (3 * Dv)      // 1536

// Scratch (device globals; no allocation allowed)
__device__ __half g_xh   [Mv * Dv];
__device__ __half g_wqkvT[QKVN * Dv];   // [Wq*s|Wk*s|Wv]^T : [N][K]
__device__ __half g_woT  [Dv * Dv];
__device__ __half g_w1T  [DEv * Dv];
__device__ __half g_w2T  [Dv * DEv];
__device__ __half g_qk   [Mv * 1024];   // q|k halves, row stride 1024
__device__ __half g_vt   [Dv * Mv];     // v transposed: [(h*64+d)][b*2048+s]
__device__ __half g_oh   [Mv * Dv];
__device__ __half g_x1h  [Mv * Dv];
__device__ __half g_hh   [Mv * DEv];
__device__ float  g_x1res[Mv * Dv];

enum { EP_QKV = 0, EP_RES = 1, EP_BIAS_GELU = 2, EP_BIAS_RES = 3 };

__device__ __forceinline__ float gelu_tanh(float x) {
    float x3 = x * x * x;
    float t = tanhf(0.7978845608028654f * (x + 0.044715f * x3));
    return 0.5f * x * (1.0f + t);
}

__device__ __forceinline__ uint32_t smem_u32(const void* p) {
    uint32_t a;
    asm("{ .reg .u64 t; cvta.to.shared.u64 t, %1; cvt.u32.u64 %0, t; }"
        : "=r"(a) : "l"(p));
    return a;
}

#define CP_ASYNC16(dst, src) \
    asm volatile("cp.async.cg.shared.global [%0], [%1], 16;" :: "r"(dst), "l"(src))
#define CP_COMMIT() asm volatile("cp.async.commit_group;" ::: "memory")
#define CP_WAIT(n)  asm volatile("cp.async.wait_group %0;" :: "n"(n) : "memory")

#define LDSM_X4(r0, r1, r2, r3, a) \
    asm volatile("ldmatrix.sync.aligned.m8n8.x4.shared.b16 {%0,%1,%2,%3}, [%4];" \
        : "=r"(r0), "=r"(r1), "=r"(r2), "=r"(r3) : "r"(a))

__device__ __forceinline__ void mma_f16(float c[4], uint32_t a0, uint32_t a1,
                                        uint32_t a2, uint32_t a3,
                                        uint32_t b0, uint32_t b1) {
    asm volatile(
        "mma.sync.aligned.m16n8k16.row.col.f32.f16.f16.f32 "
        "{%0,%1,%2,%3}, {%4,%5,%6,%7}, {%8,%9}, {%0,%1,%2,%3};"
        : "+f"(c[0]), "+f"(c[1]), "+f"(c[2]), "+f"(c[3])
        : "r"(a0), "r"(a1), "r"(a2), "r"(a3), "r"(b0), "r"(b1));
}

// ---------------------------------------------------------------------------
// Fused preprocessing (one launch): 6 weight transposes + x convert.
// scale for Wq/Wk includes sqrt(log2(e)) so scores land in log2 domain.
// ---------------------------------------------------------------------------
__device__ __forceinline__ void transpose_tile(
    const float* __restrict__ src, __half* __restrict__ dst,
    int R, int C, float scale, int bx, int by)
{
    __shared__ float t[32][33];
    const int tx = threadIdx.x, ty = threadIdx.y;
#pragma unroll
    for (int j = 0; j < 4; j++)
        t[ty + 8 * j][tx] = src[(size_t)(by * 32 + ty + 8 * j) * C + bx * 32 + tx];
    __syncthreads();
#pragma unroll
    for (int j = 0; j < 4; j++)
        dst[(size_t)(bx * 32 + ty + 8 * j) * R + by * 32 + tx] =
            __float2half_rn(t[tx][ty + 8 * j] * scale);
}

__global__ __launch_bounds__(256)
void prep_all(const float* __restrict__ x,  const float* __restrict__ Wq,
              const float* __restrict__ Wk, const float* __restrict__ Wv,
              const float* __restrict__ Wo, const float* __restrict__ W1,
              const float* __restrict__ W2, float scale)
{
    const int gb = blockIdx.x;
    if (gb < 256) {
        transpose_tile(Wq, g_wqkvT,             Dv, Dv, scale, gb & 15, gb >> 4);
    } else if (gb < 512) {
        int t = gb - 256;
        transpose_tile(Wk, g_wqkvT + 512 * Dv,  Dv, Dv, scale, t & 15, t >> 4);
    } else if (gb < 768) {
        int t = gb - 512;
        transpose_tile(Wv, g_wqkvT + 1024 * Dv, Dv, Dv, 1.0f, t & 15, t >> 4);
    } else if (gb < 1024) {
        int t = gb - 768;
        transpose_tile(Wo, g_woT, Dv, Dv, 1.0f, t & 15, t >> 4);
    } else if (gb < 2048) {
        int t = gb - 1024;                      // W1: R=512, C=2048, grid 64x16
        transpose_tile(W1, g_w1T, Dv, DEv, 1.0f, t & 63, t >> 6);
    } else if (gb < 3072) {
        int t = gb - 2048;                      // W2: R=2048, C=512, grid 16x64
        transpose_tile(W2, g_w2T, DEv, Dv, 1.0f, t & 15, t >> 4);
    } else {
        int t = gb - 3072;
        int tid = threadIdx.y * 32 + threadIdx.x;
        int i = t * 256 + tid;
        for (int idx = i; idx < Mv * Dv / 2; idx += 256 * 256) {
            float2 v = *(const float2*)(x + 2 * idx);
            *(__half2*)(g_xh + 2 * idx) = __floats2half2_rn(v.x, v.y);
        }
    }
}

// ---------------------------------------------------------------------------
// fp16 GEMM: 5-stage cp.async ring (4 groups in flight), ldmatrix, m16n8k16.
// Unchanged from round 11.
// ---------------------------------------------------------------------------
#define HS 40
#define STG_HALFS (2 * 128 * HS)                 // 10240
#define GEMM_SMEM (5 * STG_HALFS * 2)            // 102400 B

template <int EPI>
__global__ __launch_bounds__(256, 2)
void gemm_mma(const __half* __restrict__ A, const __half* __restrict__ BT,
              const float* __restrict__ bias, const float* __restrict__ res,
              float* __restrict__ Cf, __half* __restrict__ Ch,
              __half* __restrict__ Vt, int M, int N, int K)
{
    extern __shared__ __half smh[];

    const int tid = threadIdx.x;
    const int wid = tid >> 5;
    const int lid = tid & 31;
    const int gid = lid >> 2;
    const int tq  = lid & 3;
    const int wm  = (wid >> 1) * 32;
    const int wn  = (wid & 1) * 64;
    const int bm  = blockIdx.y * 128;
    const int bn  = blockIdx.x * 128;
    const int NS  = K >> 5;

    const int lrow = (lid & 7) + ((lid >> 3) & 1) * 8;
    const int ak16 = lid >> 4;
    const int brow = lid & 7;
    const int bk16 = (lid >> 3) & 1;
    const int bn8  = (lid >> 4) & 1;

    auto issue = [&](int s, int buf) {
        __half* ab = smh + buf * STG_HALFS;
        __half* bb = ab + 128 * HS;
        const __half* Ap = A  + (size_t)bm * K + s * 32;
        const __half* Bp = BT + (size_t)bn * K + s * 32;
#pragma unroll
        for (int it = 0; it < 2; it++) {
            int idx = it * 256 + tid;
            int r = idx >> 2, c = (idx & 3) * 8;
            CP_ASYNC16(smem_u32(ab + r * HS + c), Ap + (size_t)r * K + c);
        }
#pragma unroll
        for (int it = 0; it < 2; it++) {
            int idx = it * 256 + tid;
            int r = idx >> 2, c = (idx & 3) * 8;
            CP_ASYNC16(smem_u32(bb + r * HS + c), Bp + (size_t)r * K + c);
        }
        CP_COMMIT();
    };

    float acc[2][8][4];
#pragma unroll
    for (int mt = 0; mt < 2; mt++)
#pragma unroll
        for (int nt = 0; nt < 8; nt++)
#pragma unroll
            for (int u = 0; u < 4; u++) acc[mt][nt][u] = 0.0f;

    issue(0, 0); issue(1, 1); issue(2, 2); issue(3, 3);

    for (int s = 0; s < NS; s++) {
        const int rem = NS - 1 - s;
        if (rem >= 3)      { CP_WAIT(3); }
        else if (rem == 2) { CP_WAIT(2); }
        else if (rem == 1) { CP_WAIT(1); }
        else               { CP_WAIT(0); }
        __syncthreads();
        if (s + 4 < NS) issue(s + 4, (s + 4) % 5);

        const uint32_t stage = smem_u32(smh + (s % 5) * STG_HALFS);
        const uint32_t a_base = stage + ((wm + lrow) * HS) * 2 + ak16 * 16;
        const uint32_t b_base = stage + 128 * HS * 2
                              + ((wn + bn8 * 8 + brow) * HS) * 2 + bk16 * 16;
#pragma unroll
        for (int ks = 0; ks < 2; ks++) {
            uint32_t a[2][4];
#pragma unroll
            for (int mt = 0; mt < 2; mt++)
                LDSM_X4(a[mt][0], a[mt][1], a[mt][2], a[mt][3],
                        a_base + mt * (16 * HS * 2) + ks * 32);
#pragma unroll
            for (int p = 0; p < 4; p++) {
                uint32_t b0, b1, b2, b3;
                LDSM_X4(b0, b1, b2, b3, b_base + p * (16 * HS * 2) + ks * 32);
#pragma unroll
                for (int mt = 0; mt < 2; mt++) {
                    mma_f16(acc[mt][2 * p],     a[mt][0], a[mt][1], a[mt][2], a[mt][3], b0, b1);
                    mma_f16(acc[mt][2 * p + 1], a[mt][0], a[mt][1], a[mt][2], a[mt][3], b2, b3);
                }
            }
        }
    }

    // Epilogue
#pragma unroll
    for (int mt = 0; mt < 2; mt++) {
#pragma unroll
        for (int half_ = 0; half_ < 2; half_++) {
            const int row = bm + wm + mt * 16 + gid + half_ * 8;
#pragma unroll
            for (int nt = 0; nt < 8; nt++) {
                const int col = bn + wn + nt * 8 + 2 * tq;
                float v0 = acc[mt][nt][half_ * 2 + 0];
                float v1 = acc[mt][nt][half_ * 2 + 1];
                if (EPI == EP_QKV) {
                    if (bn < 1024) {
                        *(__half2*)(Ch + (size_t)row * 1024 + col) =
                            __floats2half2_rn(v0, v1);
                    } else {
                        Vt[(size_t)(col - 1024) * Mv + row] = __float2half_rn(v0);
                        Vt[(size_t)(col - 1023) * Mv + row] = __float2half_rn(v1);
                    }
                } else if (EPI == EP_RES) {
                    v0 += res[(size_t)row * N + col];
                    v1 += res[(size_t)row * N + col + 1];
                    *(float2*)(Cf + (size_t)row * N + col) = make_float2(v0, v1);
                    *(__half2*)(Ch + (size_t)row * N + col) = __floats2half2_rn(v0, v1);
                } else if (EPI == EP_BIAS_GELU) {
                    v0 = gelu_tanh(v0 + bias[col]);
                    v1 = gelu_tanh(v1 + bias[col + 1]);
                    *(__half2*)(Ch + (size_t)row * N + col) = __floats2half2_rn(v0, v1);
                } else {   // EP_BIAS_RES
                    v0 += bias[col]     + res[(size_t)row * N + col];
                    v1 += bias[col + 1] + res[(size_t)row * N + col + 1];
                    *(float2*)(Cf + (size_t)row * N + col) = make_float2(v0, v1);
                }
            }
        }
    }
}

// ---------------------------------------------------------------------------
// fp16 flash attention: 128 q-rows/CTA, 256 threads, 2 CTA/SM (round-11 shape)
// + h2exp2 softmax (log2-domain scores) + register P-fragment reuse
//   (S C-fragments ARE the PV A-fragments; no P SMEM round-trip).
// 4-stage cp.async K+V ring (3 tiles in flight).
// SMEM (halfs): ring 4 x 9216 = 36864; Qs at 36864 (9216). 92160 B total.
// ---------------------------------------------------------------------------
#define ATTN_SMEM ((4 * 9216 + 9216) * 2)   // 92160 B
#define NT_TILES (Sv / 64)                  // 32

__global__ __launch_bounds__(256, 2)
void attn_mma(const __half* __restrict__ qk, const __half* __restrict__ vt,
              __half* __restrict__ o)
{
    extern __shared__ __half smh[];
    __half* Qs = smh + 36864;

    const int tid = threadIdx.x;
    const int wid = tid >> 5;
    const int lid = tid & 31;
    const int gid = lid >> 2;
    const int tq  = lid & 3;
    const int qt  = blockIdx.x;     // 0..15
    const int h   = blockIdx.y;
    const int b   = blockIdx.z;

    const int lrow = (lid & 7) + ((lid >> 3) & 1) * 8;
    const int ak16 = lid >> 4;
    const int brow = lid & 7;
    const int bk16 = (lid >> 3) & 1;
    const int bn8  = (lid >> 4) & 1;

    const __half* qb  = qk + ((size_t)b * Sv + qt * 128) * 1024 + h * HDv;
    const __half* kb  = qk + (size_t)b * Sv * 1024 + 512 + h * HDv;
    const __half* vtb = vt + (size_t)(h * HDv) * Mv + b * Sv;

    auto issue_tile = [&](int kt, int buf) {
#pragma unroll
        for (int it = 0; it < 2; it++) {       // K: [key][72]
            int idx = it * 256 + tid;
            int key = idx >> 3, ch = (idx & 7) * 8;
            CP_ASYNC16(smem_u32(smh + buf * 9216 + key * 72 + ch),
                       kb + (size_t)(kt * 64 + key) * 1024 + ch);
        }
#pragma unroll
        for (int it = 0; it < 2; it++) {       // V: [d][72]
            int idx = it * 256 + tid;
            int d = idx >> 3, ch = (idx & 7) * 8;
            CP_ASYNC16(smem_u32(smh + buf * 9216 + 4608 + d * 72 + ch),
                       vtb + (size_t)d * Mv + kt * 64 + ch);
        }
        CP_COMMIT();
    };

    issue_tile(0, 0);

    // Stage Q [128][72] via cp.async (own group)
#pragma unroll
    for (int it = 0; it < 4; it++) {
        int idx = it * 256 + tid;
        int r = idx >> 3, c = (idx & 7) * 8;
        CP_ASYNC16(smem_u32(Qs + r * 72 + c), qb + (size_t)r * 1024 + c);
    }
    CP_COMMIT();
    issue_tile(1, 1);
    issue_tile(2, 2);

    CP_WAIT(2);          // tile0 + Q complete; tiles 1,2 in flight
    __syncthreads();

    uint32_t qf[4][4];
    {
        const uint32_t qaddr = smem_u32(Qs) + ((wid * 16 + lrow) * 72) * 2 + ak16 * 16;
#pragma unroll
        for (int ks = 0; ks < 4; ks++)
            LDSM_X4(qf[ks][0], qf[ks][1], qf[ks][2], qf[ks][3], qaddr + ks * 32);
    }

    float oacc[8][4];
#pragma unroll
    for (int dt = 0; dt < 8; dt++)
#pragma unroll
        for (int u = 0; u < 4; u++) oacc[dt][u] = 0.0f;
    float mrow0 = -1e30f, mrow1 = -1e30f, lrow0 = 0.0f, lrow1 = 0.0f;

    for (int kt = 0; kt < NT_TILES; kt++) {
        const int buf = kt & 3;
        const int rem = NT_TILES - 1 - kt;
        if (rem >= 2)      { CP_WAIT(2); }
        else if (rem == 1) { CP_WAIT(1); }
        else               { CP_WAIT(0); }
        __syncthreads();
        if (kt + 3 < NT_TILES) issue_tile(kt + 3, (kt + 3) & 3);

        const uint32_t kaddr = smem_u32(smh + buf * 9216)
                             + ((bn8 * 8 + brow) * 72) * 2 + bk16 * 16;
        const uint32_t vaddr = smem_u32(smh + buf * 9216 + 4608)
                             + ((bn8 * 8 + brow) * 72) * 2 + bk16 * 16;

        // ---- S = Q @ K^T (log2-domain scores) ----
        float sacc[8][4];
#pragma unroll
        for (int nt = 0; nt < 8; nt++)
#pragma unroll
            for (int u = 0; u < 4; u++) sacc[nt][u] = 0.0f;
#pragma unroll
        for (int ks = 0; ks < 4; ks++) {
#pragma unroll
            for (int p = 0; p < 4; p++) {
                uint32_t b0, b1, b2, b3;
                LDSM_X4(b0, b1, b2, b3, kaddr + p * (16 * 72 * 2) + ks * 32);
                mma_f16(sacc[2 * p],     qf[ks][0], qf[ks][1], qf[ks][2], qf[ks][3], b0, b1);
                mma_f16(sacc[2 * p + 1], qf[ks][0], qf[ks][1], qf[ks][2], qf[ks][3], b2, b3);
            }
        }

        // ---- online softmax: h2exp2 into register P-fragments ----
        float mx0 = -1e30f, mx1 = -1e30f;
#pragma unroll
        for (int nt = 0; nt < 8; nt++) {
            mx0 = fmaxf(mx0, fmaxf(sacc[nt][0], sacc[nt][1]));
            mx1 = fmaxf(mx1, fmaxf(sacc[nt][2], sacc[nt][3]));
        }
        mx0 = fmaxf(mx0, __shfl_xor_sync(0xffffffffu, mx0, 1));
        mx0 = fmaxf(mx0, __shfl_xor_sync(0xffffffffu, mx0, 2));
        mx1 = fmaxf(mx1, __shfl_xor_sync(0xffffffffu, mx1, 1));
        mx1 = fmaxf(mx1, __shfl_xor_sync(0xffffffffu, mx1, 2));
        float mn0 = fmaxf(mrow0, mx0), mn1 = fmaxf(mrow1, mx1);
        float corr0 = exp2f(mrow0 - mn0), corr1 = exp2f(mrow1 - mn1);

        uint32_t pf[8], pg[8];    // P fragments: rows gid / gid+8
        float ps0 = 0.0f, ps1 = 0.0f;
#pragma unroll
        for (int nt = 0; nt < 8; nt++) {
            __half2 e0 = h2exp2(__floats2half2_rn(sacc[nt][0] - mn0, sacc[nt][1] - mn0));
            __half2 e1 = h2exp2(__floats2half2_rn(sacc[nt][2] - mn1, sacc[nt][3] - mn1));
            pf[nt] = *reinterpret_cast<uint32_t*>(&e0);
            pg[nt] = *reinterpret_cast<uint32_t*>(&e1);
            float2 f0 = __half22float2(e0);
            float2 f1 = __half22float2(e1);
            ps0 += f0.x + f0.y;
            ps1 += f1.x + f1.y;
        }
        ps0 += __shfl_xor_sync(0xffffffffu, ps0, 1);
        ps0 += __shfl_xor_sync(0xffffffffu, ps0, 2);
        ps1 += __shfl_xor_sync(0xffffffffu, ps1, 1);
        ps1 += __shfl_xor_sync(0xffffffffu, ps1, 2);
        lrow0 = lrow0 * corr0 + ps0;
        lrow1 = lrow1 * corr1 + ps1;
        mrow0 = mn0; mrow1 = mn1;
#pragma unroll
        for (int dt = 0; dt < 8; dt++) {
            oacc[dt][0] *= corr0; oacc[dt][1] *= corr0;
            oacc[dt][2] *= corr1; oacc[dt][3] *= corr1;
        }

        // ---- O += P @ V (P fragments straight from registers) ----
#pragma unroll
        for (int ks = 0; ks < 4; ks++) {
            uint32_t pa0 = pf[2 * ks],     pa1 = pg[2 * ks];
            uint32_t pa2 = pf[2 * ks + 1], pa3 = pg[2 * ks + 1];
#pragma unroll
            for (int p = 0; p < 4; p++) {
                uint32_t b0, b1, b2, b3;
                LDSM_X4(b0, b1, b2, b3, vaddr + p * (16 * 72 * 2) + ks * 32);
                mma_f16(oacc[2 * p],     pa0, pa1, pa2, pa3, b0, b1);
                mma_f16(oacc[2 * p + 1], pa0, pa1, pa2, pa3, b2, b3);
            }
        }
    }

    // ---- normalize, write O (half) ----
    float inv0 = 1.0f / lrow0, inv1 = 1.0f / lrow1;
    __half* ob = o + ((size_t)b * Sv + qt * 128 + wid * 16) * Dv + h * HDv;
#pragma unroll
    for (int dt = 0; dt < 8; dt++) {
        int col = dt * 8 + 2 * tq;
        *(__half2*)(ob + (size_t)gid * Dv + col) =
            __floats2half2_rn(oacc[dt][0] * inv0, oacc[dt][1] * inv0);
        *(__half2*)(ob + (size_t)(gid + 8) * Dv + col) =
            __floats2half2_rn(oacc[dt][2] * inv1, oacc[dt][3] * inv1);
    }
}

// ---------------------------------------------------------------------------
// Launch
// ---------------------------------------------------------------------------
extern "C" void kernel_launch(void* const* d_in, const int* in_sizes, int n_in,
                              void* d_out, int out_size)
{
    const float* x  = (const float*)d_in[0];
    const float* Wq = (const float*)d_in[1];
    const float* Wk = (const float*)d_in[2];
    const float* Wv = (const float*)d_in[3];
    const float* Wo = (const float*)d_in[4];
    const float* W1 = (const float*)d_in[5];
    const float* b1 = (const float*)d_in[6];
    const float* W2 = (const float*)d_in[7];
    const float* b2 = (const float*)d_in[8];
    float* out = (float*)d_out;

    __half *xh, *wqkvT, *woT, *w1T, *w2T, *qk, *vt, *oh, *x1h, *hh;
    float* x1res;
    cudaGetSymbolAddress((void**)&xh,    g_xh);
    cudaGetSymbolAddress((void**)&wqkvT, g_wqkvT);
    cudaGetSymbolAddress((void**)&woT,   g_woT);
    cudaGetSymbolAddress((void**)&w1T,   g_w1T);
    cudaGetSymbolAddress((void**)&w2T,   g_w2T);
    cudaGetSymbolAddress((void**)&qk,    g_qk);
    cudaGetSymbolAddress((void**)&vt,    g_vt);
    cudaGetSymbolAddress((void**)&oh,    g_oh);
    cudaGetSymbolAddress((void**)&x1h,   g_x1h);
    cudaGetSymbolAddress((void**)&hh,    g_hh);
    cudaGetSymbolAddress((void**)&x1res, g_x1res);

    cudaFuncSetAttribute(gemm_mma<EP_QKV>,       cudaFuncAttributeMaxDynamicSharedMemorySize, GEMM_SMEM);
    cudaFuncSetAttribute(gemm_mma<EP_RES>,       cudaFuncAttributeMaxDynamicSharedMemorySize, GEMM_SMEM);
    cudaFuncSetAttribute(gemm_mma<EP_BIAS_GELU>, cudaFuncAttributeMaxDynamicSharedMemorySize, GEMM_SMEM);
    cudaFuncSetAttribute(gemm_mma<EP_BIAS_RES>,  cudaFuncAttributeMaxDynamicSharedMemorySize, GEMM_SMEM);
    cudaFuncSetAttribute(attn_mma, cudaFuncAttributeMaxDynamicSharedMemorySize, ATTN_SMEM);

    // 512^(-0.25) * sqrt(log2(e)) -> scores come out of QK^T in log2 domain
    const float scale = 0.21022410381342865f * 1.2011224087864498f;
    dim3 blk(256);

    prep_all<<<3328, dim3(32, 8)>>>(x, Wq, Wk, Wv, Wo, W1, W2, scale);

    // qkv projections: q|k -> g_qk, v -> g_vt (transposed)
    gemm_mma<EP_QKV><<<dim3(QKVN / 128, Mv / 128), blk, GEMM_SMEM>>>(
        xh, wqkvT, nullptr, nullptr, nullptr, qk, vt, Mv, QKVN, Dv);

    attn_mma<<<dim3(Sv / 128, Hv, Bv), blk, ATTN_SMEM>>>(qk, vt, oh);

    // x1 = o @ Wo + x   (fp32 res + half copy)
    gemm_mma<EP_RES><<<dim3(Dv / 128, Mv / 128), blk, GEMM_SMEM>>>(
        oh, woT, nullptr, x, x1res, x1h, nullptr, Mv, Dv, Dv);
    // h = gelu(x1 @ W1 + b1)
    gemm_mma<EP_BIAS_GELU><<<dim3(DEv / 128, Mv / 128), blk, GEMM_SMEM>>>(
        x1h, w1T, b1, nullptr, nullptr, hh, nullptr, Mv, DEv, Dv);
    // out = h @ W2 + b2 + x1
    gemm_mma<EP_BIAS_RES><<<dim3(Dv / 128, Mv / 128), blk, GEMM_SMEM>>>(
        hh, w2T, b2, x1res, out, nullptr, nullptr, Mv, Dv, DEv);
}

// round 14
// speedup vs baseline: 1.0921x; 1.0675x over previous
#include <cuda_runtime.h>
#include <cuda_fp16.h>
#include <math.h>
#include <stdint.h>

// Problem constants
#define Bv   4
#define Sv   2048
#define Dv   512
#define Hv   8
#define Ev   4
#define HDv  64
#define Mv   (Bv * Sv)     // 8192
#define DEv  (Dv * Ev)     // 2048
#define QKVN (3 * Dv)      // 1536

// Scratch (device globals; no allocation allowed)
__device__ __half g_xh   [Mv * Dv];
__device__ __half g_wqkvT[QKVN * Dv];   // [Wq*s|Wk*s|Wv]^T : [N][K]
__device__ __half g_woT  [Dv * Dv];
__device__ __half g_w1T  [DEv * Dv];
__device__ __half g_w2T  [Dv * DEv];
__device__ __half g_qk   [Mv * 1024];   // q|k halves, row stride 1024
__device__ __half g_vt   [Dv * Mv];     // v transposed: [(h*64+d)][b*2048+s]
__device__ __half g_oh   [Mv * Dv];
__device__ __half g_x1h  [Mv * Dv];
__device__ __half g_hh   [Mv * DEv];
__device__ float  g_x1res[Mv * Dv];

enum { EP_QKV = 0, EP_RES = 1, EP_BIAS_GELU = 2, EP_BIAS_RES = 3 };

__device__ __forceinline__ float gelu_tanh(float x) {
    float x3 = x * x * x;
    float t = tanhf(0.7978845608028654f * (x + 0.044715f * x3));
    return 0.5f * x * (1.0f + t);
}

__device__ __forceinline__ uint32_t smem_u32(const void* p) {
    uint32_t a;
    asm("{ .reg .u64 t; cvta.to.shared.u64 t, %1; cvt.u32.u64 %0, t; }"
        : "=r"(a) : "l"(p));
    return a;
}

#define CP_ASYNC16(dst, src) \
    asm volatile("cp.async.cg.shared.global [%0], [%1], 16;" :: "r"(dst), "l"(src))
#define CP_COMMIT() asm volatile("cp.async.commit_group;" ::: "memory")
#define CP_WAIT(n)  asm volatile("cp.async.wait_group %0;" :: "n"(n) : "memory")

#define LDSM_X4(r0, r1, r2, r3, a) \
    asm volatile("ldmatrix.sync.aligned.m8n8.x4.shared.b16 {%0,%1,%2,%3}, [%4];" \
        : "=r"(r0), "=r"(r1), "=r"(r2), "=r"(r3) : "r"(a))

__device__ __forceinline__ void mma_f16(float c[4], uint32_t a0, uint32_t a1,
                                        uint32_t a2, uint32_t a3,
                                        uint32_t b0, uint32_t b1) {
    asm volatile(
        "mma.sync.aligned.m16n8k16.row.col.f32.f16.f16.f32 "
        "{%0,%1,%2,%3}, {%4,%5,%6,%7}, {%8,%9}, {%0,%1,%2,%3};"
        : "+f"(c[0]), "+f"(c[1]), "+f"(c[2]), "+f"(c[3])
        : "r"(a0), "r"(a1), "r"(a2), "r"(a3), "r"(b0), "r"(b1));
}

// ---------------------------------------------------------------------------
// Fused preprocessing (one launch): 6 weight transposes + x convert.
// scale for Wq/Wk includes sqrt(log2(e)) so scores land in log2 domain.
// ---------------------------------------------------------------------------
__device__ __forceinline__ void transpose_tile(
    const float* __restrict__ src, __half* __restrict__ dst,
    int R, int C, float scale, int bx, int by)
{
    __shared__ float t[32][33];
    const int tx = threadIdx.x, ty = threadIdx.y;
#pragma unroll
    for (int j = 0; j < 4; j++)
        t[ty + 8 * j][tx] = src[(size_t)(by * 32 + ty + 8 * j) * C + bx * 32 + tx];
    __syncthreads();
#pragma unroll
    for (int j = 0; j < 4; j++)
        dst[(size_t)(bx * 32 + ty + 8 * j) * R + by * 32 + tx] =
            __float2half_rn(t[tx][ty + 8 * j] * scale);
}

__global__ __launch_bounds__(256)
void prep_all(const float* __restrict__ x,  const float* __restrict__ Wq,
              const float* __restrict__ Wk, const float* __restrict__ Wv,
              const float* __restrict__ Wo, const float* __restrict__ W1,
              const float* __restrict__ W2, float scale)
{
    const int gb = blockIdx.x;
    if (gb < 256) {
        transpose_tile(Wq, g_wqkvT,             Dv, Dv, scale, gb & 15, gb >> 4);
    } else if (gb < 512) {
        int t = gb - 256;
        transpose_tile(Wk, g_wqkvT + 512 * Dv,  Dv, Dv, scale, t & 15, t >> 4);
    } else if (gb < 768) {
        int t = gb - 512;
        transpose_tile(Wv, g_wqkvT + 1024 * Dv, Dv, Dv, 1.0f, t & 15, t >> 4);
    } else if (gb < 1024) {
        int t = gb - 768;
        transpose_tile(Wo, g_woT, Dv, Dv, 1.0f, t & 15, t >> 4);
    } else if (gb < 2048) {
        int t = gb - 1024;                      // W1: R=512, C=2048, grid 64x16
        transpose_tile(W1, g_w1T, Dv, DEv, 1.0f, t & 63, t >> 6);
    } else if (gb < 3072) {
        int t = gb - 2048;                      // W2: R=2048, C=512, grid 16x64
        transpose_tile(W2, g_w2T, DEv, Dv, 1.0f, t & 15, t >> 4);
    } else {
        int t = gb - 3072;
        int tid = threadIdx.y * 32 + threadIdx.x;
        int i = t * 256 + tid;
        for (int idx = i; idx < Mv * Dv / 2; idx += 256 * 256) {
            float2 v = *(const float2*)(x + 2 * idx);
            *(__half2*)(g_xh + 2 * idx) = __floats2half2_rn(v.x, v.y);
        }
    }
}

// ---------------------------------------------------------------------------
// fp16 GEMM: BK=64 slabs (half the barriers), 3-stage cp.async ring
// (2 stages in flight), ldmatrix, m16n8k16.
// A: [M,K] half; BT: [N,K] half; CTA 128x128, 256 thr, warps 4Mx2N.
// Stage: A[128][72] + B[128][72] halfs (144B rows, ldmatrix conflict-free).
// ---------------------------------------------------------------------------
#define GHS 72
#define STG_HALFS (2 * 128 * GHS)                // 18432
#define GEMM_SMEM (3 * STG_HALFS * 2)            // 110592 B

template <int EPI>
__global__ __launch_bounds__(256, 2)
void gemm_mma(const __half* __restrict__ A, const __half* __restrict__ BT,
              const float* __restrict__ bias, const float* __restrict__ res,
              float* __restrict__ Cf, __half* __restrict__ Ch,
              __half* __restrict__ Vt, int M, int N, int K)
{
    extern __shared__ __half smh[];

    const int tid = threadIdx.x;
    const int wid = tid >> 5;
    const int lid = tid & 31;
    const int gid = lid >> 2;
    const int tq  = lid & 3;
    const int wm  = (wid >> 1) * 32;
    const int wn  = (wid & 1) * 64;
    const int bm  = blockIdx.y * 128;
    const int bn  = blockIdx.x * 128;
    const int NS  = K >> 6;

    const int lrow = (lid & 7) + ((lid >> 3) & 1) * 8;
    const int ak16 = lid >> 4;
    const int brow = lid & 7;
    const int bk16 = (lid >> 3) & 1;
    const int bn8  = (lid >> 4) & 1;

    auto issue = [&](int s, int buf) {
        __half* ab = smh + buf * STG_HALFS;
        __half* bb = ab + 128 * GHS;
        const __half* Ap = A  + (size_t)bm * K + s * 64;
        const __half* Bp = BT + (size_t)bn * K + s * 64;
        // 128 rows x 64 halfs = 1024 16B chunks each; 4 per thread
#pragma unroll
        for (int it = 0; it < 4; it++) {
            int idx = it * 256 + tid;
            int r = idx >> 3, c = (idx & 7) * 8;
            CP_ASYNC16(smem_u32(ab + r * GHS + c), Ap + (size_t)r * K + c);
        }
#pragma unroll
        for (int it = 0; it < 4; it++) {
            int idx = it * 256 + tid;
            int r = idx >> 3, c = (idx & 7) * 8;
            CP_ASYNC16(smem_u32(bb + r * GHS + c), Bp + (size_t)r * K + c);
        }
        CP_COMMIT();
    };

    float acc[2][8][4];
#pragma unroll
    for (int mt = 0; mt < 2; mt++)
#pragma unroll
        for (int nt = 0; nt < 8; nt++)
#pragma unroll
            for (int u = 0; u < 4; u++) acc[mt][nt][u] = 0.0f;

    issue(0, 0);
    issue(1, 1);

    for (int s = 0; s < NS; s++) {
        if (s == NS - 1) { CP_WAIT(0); } else { CP_WAIT(1); }
        __syncthreads();   // stage s visible; all warps done with stage s-1
        if (s + 2 < NS) issue(s + 2, (s + 2) % 3);

        const uint32_t stage = smem_u32(smh + (s % 3) * STG_HALFS);
        const uint32_t a_base = stage + ((wm + lrow) * GHS) * 2 + ak16 * 16;
        const uint32_t b_base = stage + 128 * GHS * 2
                              + ((wn + bn8 * 8 + brow) * GHS) * 2 + bk16 * 16;
#pragma unroll
        for (int ks = 0; ks < 4; ks++) {
            uint32_t a[2][4];
#pragma unroll
            for (int mt = 0; mt < 2; mt++)
                LDSM_X4(a[mt][0], a[mt][1], a[mt][2], a[mt][3],
                        a_base + mt * (16 * GHS * 2) + ks * 32);
#pragma unroll
            for (int p = 0; p < 4; p++) {
                uint32_t b0, b1, b2, b3;
                LDSM_X4(b0, b1, b2, b3, b_base + p * (16 * GHS * 2) + ks * 32);
#pragma unroll
                for (int mt = 0; mt < 2; mt++) {
                    mma_f16(acc[mt][2 * p],     a[mt][0], a[mt][1], a[mt][2], a[mt][3], b0, b1);
                    mma_f16(acc[mt][2 * p + 1], a[mt][0], a[mt][1], a[mt][2], a[mt][3], b2, b3);
                }
            }
        }
    }

    // Epilogue
#pragma unroll
    for (int mt = 0; mt < 2; mt++) {
#pragma unroll
        for (int half_ = 0; half_ < 2; half_++) {
            const int row = bm + wm + mt * 16 + gid + half_ * 8;
#pragma unroll
            for (int nt = 0; nt < 8; nt++) {
                const int col = bn + wn + nt * 8 + 2 * tq;
                float v0 = acc[mt][nt][half_ * 2 + 0];
                float v1 = acc[mt][nt][half_ * 2 + 1];
                if (EPI == EP_QKV) {
                    if (bn < 1024) {
                        *(__half2*)(Ch + (size_t)row * 1024 + col) =
                            __floats2half2_rn(v0, v1);
                    } else {
                        Vt[(size_t)(col - 1024) * Mv + row] = __float2half_rn(v0);
                        Vt[(size_t)(col - 1023) * Mv + row] = __float2half_rn(v1);
                    }
                } else if (EPI == EP_RES) {
                    v0 += res[(size_t)row * N + col];
                    v1 += res[(size_t)row * N + col + 1];
                    *(float2*)(Cf + (size_t)row * N + col) = make_float2(v0, v1);
                    *(__half2*)(Ch + (size_t)row * N + col) = __floats2half2_rn(v0, v1);
                } else if (EPI == EP_BIAS_GELU) {
                    v0 = gelu_tanh(v0 + bias[col]);
                    v1 = gelu_tanh(v1 + bias[col + 1]);
                    *(__half2*)(Ch + (size_t)row * N + col) = __floats2half2_rn(v0, v1);
                } else {   // EP_BIAS_RES
                    v0 += bias[col]     + res[(size_t)row * N + col];
                    v1 += bias[col + 1] + res[(size_t)row * N + col + 1];
                    *(float2*)(Cf + (size_t)row * N + col) = make_float2(v0, v1);
                }
            }
        }
    }
}

// ---------------------------------------------------------------------------
// fp16 flash attention (unchanged from round 13): 128 q-rows/CTA, 256 thr,
// 2 CTA/SM, 4-stage cp.async ring, h2exp2 softmax, register P-fragments.
// ---------------------------------------------------------------------------
#define ATTN_SMEM ((4 * 9216 + 9216) * 2)   // 92160 B
#define NT_TILES (Sv / 64)                  // 32

__global__ __launch_bounds__(256, 2)
void attn_mma(const __half* __restrict__ qk, const __half* __restrict__ vt,
              __half* __restrict__ o)
{
    extern __shared__ __half smh[];
    __half* Qs = smh + 36864;

    const int tid = threadIdx.x;
    const int wid = tid >> 5;
    const int lid = tid & 31;
    const int gid = lid >> 2;
    const int tq  = lid & 3;
    const int qt  = blockIdx.x;
    const int h   = blockIdx.y;
    const int b   = blockIdx.z;

    const int lrow = (lid & 7) + ((lid >> 3) & 1) * 8;
    const int ak16 = lid >> 4;
    const int brow = lid & 7;
    const int bk16 = (lid >> 3) & 1;
    const int bn8  = (lid >> 4) & 1;

    const __half* qb  = qk + ((size_t)b * Sv + qt * 128) * 1024 + h * HDv;
    const __half* kb  = qk + (size_t)b * Sv * 1024 + 512 + h * HDv;
    const __half* vtb = vt + (size_t)(h * HDv) * Mv + b * Sv;

    auto issue_tile = [&](int kt, int buf) {
#pragma unroll
        for (int it = 0; it < 2; it++) {       // K: [key][72]
            int idx = it * 256 + tid;
            int key = idx >> 3, ch = (idx & 7) * 8;
            CP_ASYNC16(smem_u32(smh + buf * 9216 + key * 72 + ch),
                       kb + (size_t)(kt * 64 + key) * 1024 + ch);
        }
#pragma unroll
        for (int it = 0; it < 2; it++) {       // V: [d][72]
            int idx = it * 256 + tid;
            int d = idx >> 3, ch = (idx & 7) * 8;
            CP_ASYNC16(smem_u32(smh + buf * 9216 + 4608 + d * 72 + ch),
                       vtb + (size_t)d * Mv + kt * 64 + ch);
        }
        CP_COMMIT();
    };

    issue_tile(0, 0);

#pragma unroll
    for (int it = 0; it < 4; it++) {
        int idx = it * 256 + tid;
        int r = idx >> 3, c = (idx & 7) * 8;
        CP_ASYNC16(smem_u32(Qs + r * 72 + c), qb + (size_t)r * 1024 + c);
    }
    CP_COMMIT();
    issue_tile(1, 1);
    issue_tile(2, 2);

    CP_WAIT(2);
    __syncthreads();

    uint32_t qf[4][4];
    {
        const uint32_t qaddr = smem_u32(Qs) + ((wid * 16 + lrow) * 72) * 2 + ak16 * 16;
#pragma unroll
        for (int ks = 0; ks < 4; ks++)
            LDSM_X4(qf[ks][0], qf[ks][1], qf[ks][2], qf[ks][3], qaddr + ks * 32);
    }

    float oacc[8][4];
#pragma unroll
    for (int dt = 0; dt < 8; dt++)
#pragma unroll
        for (int u = 0; u < 4; u++) oacc[dt][u] = 0.0f;
    float mrow0 = -1e30f, mrow1 = -1e30f, lrow0 = 0.0f, lrow1 = 0.0f;

    for (int kt = 0; kt < NT_TILES; kt++) {
        const int buf = kt & 3;
        const int rem = NT_TILES - 1 - kt;
        if (rem >= 2)      { CP_WAIT(2); }
        else if (rem == 1) { CP_WAIT(1); }
        else               { CP_WAIT(0); }
        __syncthreads();
        if (kt + 3 < NT_TILES) issue_tile(kt + 3, (kt + 3) & 3);

        const uint32_t kaddr = smem_u32(smh + buf * 9216)
                             + ((bn8 * 8 + brow) * 72) * 2 + bk16 * 16;
        const uint32_t vaddr = smem_u32(smh + buf * 9216 + 4608)
                             + ((bn8 * 8 + brow) * 72) * 2 + bk16 * 16;

        float sacc[8][4];
#pragma unroll
        for (int nt = 0; nt < 8; nt++)
#pragma unroll
            for (int u = 0; u < 4; u++) sacc[nt][u] = 0.0f;
#pragma unroll
        for (int ks = 0; ks < 4; ks++) {
#pragma unroll
            for (int p = 0; p < 4; p++) {
                uint32_t b0, b1, b2, b3;
                LDSM_X4(b0, b1, b2, b3, kaddr + p * (16 * 72 * 2) + ks * 32);
                mma_f16(sacc[2 * p],     qf[ks][0], qf[ks][1], qf[ks][2], qf[ks][3], b0, b1);
                mma_f16(sacc[2 * p + 1], qf[ks][0], qf[ks][1], qf[ks][2], qf[ks][3], b2, b3);
            }
        }

        float mx0 = -1e30f, mx1 = -1e30f;
#pragma unroll
        for (int nt = 0; nt < 8; nt++) {
            mx0 = fmaxf(mx0, fmaxf(sacc[nt][0], sacc[nt][1]));
            mx1 = fmaxf(mx1, fmaxf(sacc[nt][2], sacc[nt][3]));
        }
        mx0 = fmaxf(mx0, __shfl_xor_sync(0xffffffffu, mx0, 1));
        mx0 = fmaxf(mx0, __shfl_xor_sync(0xffffffffu, mx0, 2));
        mx1 = fmaxf(mx1, __shfl_xor_sync(0xffffffffu, mx1, 1));
        mx1 = fmaxf(mx1, __shfl_xor_sync(0xffffffffu, mx1, 2));
        float mn0 = fmaxf(mrow0, mx0), mn1 = fmaxf(mrow1, mx1);
        float corr0 = exp2f(mrow0 - mn0), corr1 = exp2f(mrow1 - mn1);

        uint32_t pf[8], pg[8];
        float ps0 = 0.0f, ps1 = 0.0f;
#pragma unroll
        for (int nt = 0; nt < 8; nt++) {
            __half2 e0 = h2exp2(__floats2half2_rn(sacc[nt][0] - mn0, sacc[nt][1] - mn0));
            __half2 e1 = h2exp2(__floats2half2_rn(sacc[nt][2] - mn1, sacc[nt][3] - mn1));
            pf[nt] = *reinterpret_cast<uint32_t*>(&e0);
            pg[nt] = *reinterpret_cast<uint32_t*>(&e1);
            float2 f0 = __half22float2(e0);
            float2 f1 = __half22float2(e1);
            ps0 += f0.x + f0.y;
            ps1 += f1.x + f1.y;
        }
        ps0 += __shfl_xor_sync(0xffffffffu, ps0, 1);
        ps0 += __shfl_xor_sync(0xffffffffu, ps0, 2);
        ps1 += __shfl_xor_sync(0xffffffffu, ps1, 1);
        ps1 += __shfl_xor_sync(0xffffffffu, ps1, 2);
        lrow0 = lrow0 * corr0 + ps0;
        lrow1 = lrow1 * corr1 + ps1;
        mrow0 = mn0; mrow1 = mn1;
#pragma unroll
        for (int dt = 0; dt < 8; dt++) {
            oacc[dt][0] *= corr0; oacc[dt][1] *= corr0;
            oacc[dt][2] *= corr1; oacc[dt][3] *= corr1;
        }

#pragma unroll
        for (int ks = 0; ks < 4; ks++) {
            uint32_t pa0 = pf[2 * ks],     pa1 = pg[2 * ks];
            uint32_t pa2 = pf[2 * ks + 1], pa3 = pg[2 * ks + 1];
#pragma unroll
            for (int p = 0; p < 4; p++) {
                uint32_t b0, b1, b2, b3;
                LDSM_X4(b0, b1, b2, b3, vaddr + p * (16 * 72 * 2) + ks * 32);
                mma_f16(oacc[2 * p],     pa0, pa1, pa2, pa3, b0, b1);
                mma_f16(oacc[2 * p + 1], pa0, pa1, pa2, pa3, b2, b3);
            }
        }
    }

    float inv0 = 1.0f / lrow0, inv1 = 1.0f / lrow1;
    __half* ob = o + ((size_t)b * Sv + qt * 128 + wid * 16) * Dv + h * HDv;
#pragma unroll
    for (int dt = 0; dt < 8; dt++) {
        int col = dt * 8 + 2 * tq;
        *(__half2*)(ob + (size_t)gid * Dv + col) =
            __floats2half2_rn(oacc[dt][0] * inv0, oacc[dt][1] * inv0);
        *(__half2*)(ob + (size_t)(gid + 8) * Dv + col) =
            __floats2half2_rn(oacc[dt][2] * inv1, oacc[dt][3] * inv1);
    }
}

// ---------------------------------------------------------------------------
// Launch
// ---------------------------------------------------------------------------
extern "C" void kernel_launch(void* const* d_in, const int* in_sizes, int n_in,
                              void* d_out, int out_size)
{
    const float* x  = (const float*)d_in[0];
    const float* Wq = (const float*)d_in[1];
    const float* Wk = (const float*)d_in[2];
    const float* Wv = (const float*)d_in[3];
    const float* Wo = (const float*)d_in[4];
    const float* W1 = (const float*)d_in[5];
    const float* b1 = (const float*)d_in[6];
    const float* W2 = (const float*)d_in[7];
    const float* b2 = (const float*)d_in[8];
    float* out = (float*)d_out;

    __half *xh, *wqkvT, *woT, *w1T, *w2T, *qk, *vt, *oh, *x1h, *hh;
    float* x1res;
    cudaGetSymbolAddress((void**)&xh,    g_xh);
    cudaGetSymbolAddress((void**)&wqkvT, g_wqkvT);
    cudaGetSymbolAddress((void**)&woT,   g_woT);
    cudaGetSymbolAddress((void**)&w1T,   g_w1T);
    cudaGetSymbolAddress((void**)&w2T,   g_w2T);
    cudaGetSymbolAddress((void**)&qk,    g_qk);
    cudaGetSymbolAddress((void**)&vt,    g_vt);
    cudaGetSymbolAddress((void**)&oh,    g_oh);
    cudaGetSymbolAddress((void**)&x1h,   g_x1h);
    cudaGetSymbolAddress((void**)&hh,    g_hh);
    cudaGetSymbolAddress((void**)&x1res, g_x1res);

    cudaFuncSetAttribute(gemm_mma<EP_QKV>,       cudaFuncAttributeMaxDynamicSharedMemorySize, GEMM_SMEM);
    cudaFuncSetAttribute(gemm_mma<EP_RES>,       cudaFuncAttributeMaxDynamicSharedMemorySize, GEMM_SMEM);
    cudaFuncSetAttribute(gemm_mma<EP_BIAS_GELU>, cudaFuncAttributeMaxDynamicSharedMemorySize, GEMM_SMEM);
    cudaFuncSetAttribute(gemm_mma<EP_BIAS_RES>,  cudaFuncAttributeMaxDynamicSharedMemorySize, GEMM_SMEM);
    cudaFuncSetAttribute(attn_mma, cudaFuncAttributeMaxDynamicSharedMemorySize, ATTN_SMEM);

    // 512^(-0.25) * sqrt(log2(e)) -> scores come out of QK^T in log2 domain
    const float scale = 0.21022410381342865f * 1.2011224087864498f;
    dim3 blk(256);

    prep_all<<<3328, dim3(32, 8)>>>(x, Wq, Wk, Wv, Wo, W1, W2, scale);

    // qkv projections: q|k -> g_qk, v -> g_vt (transposed)
    gemm_mma<EP_QKV><<<dim3(QKVN / 128, Mv / 128), blk, GEMM_SMEM>>>(
        xh, wqkvT, nullptr, nullptr, nullptr, qk, vt, Mv, QKVN, Dv);

    attn_mma<<<dim3(Sv / 128, Hv, Bv), blk, ATTN_SMEM>>>(qk, vt, oh);

    // x1 = o @ Wo + x   (fp32 res + half copy)
    gemm_mma<EP_RES><<<dim3(Dv / 128, Mv / 128), blk, GEMM_SMEM>>>(
        oh, woT, nullptr, x, x1res, x1h, nullptr, Mv, Dv, Dv);
    // h = gelu(x1 @ W1 + b1)
    gemm_mma<EP_BIAS_GELU><<<dim3(DEv / 128, Mv / 128), blk, GEMM_SMEM>>>(
        x1h, w1T, b1, nullptr, nullptr, hh, nullptr, Mv, DEv, Dv);
    // out = h @ W2 + b2 + x1
    gemm_mma<EP_BIAS_RES><<<dim3(Dv / 128, Mv / 128), blk, GEMM_SMEM>>>(
        hh, w2T, b2, x1res, out, nullptr, nullptr, Mv, Dv, DEv);
}

// round 15
// speedup vs baseline: 1.1183x; 1.0240x over previous
#include <cuda_runtime.h>
#include <cuda_fp16.h>
#include <math.h>
#include <stdint.h>

// Problem constants
#define Bv   4
#define Sv   2048
#define Dv   512
#define Hv   8
#define Ev   4
#define HDv  64
#define Mv   (Bv * Sv)     // 8192
#define DEv  (Dv * Ev)     // 2048
#define QKVN (3 * Dv)      // 1536

// Scratch (device globals; no allocation allowed)
__device__ __half g_xh   [Mv * Dv];
__device__ __half g_wqkvT[QKVN * Dv];   // [Wq*s|Wk*s|Wv]^T : [N][K]
__device__ __half g_woT  [Dv * Dv];
__device__ __half g_w1T  [DEv * Dv];
__device__ __half g_w2T  [Dv * DEv];
__device__ __half g_qk   [Mv * 1024];   // q|k halves, row stride 1024
__device__ __half g_vt   [Dv * Mv];     // v transposed: [(h*64+d)][b*2048+s]
__device__ __half g_oh   [Mv * Dv];
__device__ __half g_x1h  [Mv * Dv];     // x1 residual+activation (half)
__device__ __half g_hh   [Mv * DEv];

enum { EP_QKV = 0, EP_RES = 1, EP_BIAS_GELU = 2, EP_BIAS_RES = 3 };

__device__ __forceinline__ float gelu_tanh(float x) {
    float x3 = x * x * x;
    float t = tanhf(0.7978845608028654f * (x + 0.044715f * x3));
    return 0.5f * x * (1.0f + t);
}

__device__ __forceinline__ uint32_t smem_u32(const void* p) {
    uint32_t a;
    asm("{ .reg .u64 t; cvta.to.shared.u64 t, %1; cvt.u32.u64 %0, t; }"
        : "=r"(a) : "l"(p));
    return a;
}

#define CP_ASYNC16(dst, src) \
    asm volatile("cp.async.cg.shared.global [%0], [%1], 16;" :: "r"(dst), "l"(src))
#define CP_COMMIT() asm volatile("cp.async.commit_group;" ::: "memory")
#define CP_WAIT(n)  asm volatile("cp.async.wait_group %0;" :: "n"(n) : "memory")

#define LDSM_X4(r0, r1, r2, r3, a) \
    asm volatile("ldmatrix.sync.aligned.m8n8.x4.shared.b16 {%0,%1,%2,%3}, [%4];" \
        : "=r"(r0), "=r"(r1), "=r"(r2), "=r"(r3) : "r"(a))

__device__ __forceinline__ void mma_f16(float c[4], uint32_t a0, uint32_t a1,
                                        uint32_t a2, uint32_t a3,
                                        uint32_t b0, uint32_t b1) {
    asm volatile(
        "mma.sync.aligned.m16n8k16.row.col.f32.f16.f16.f32 "
        "{%0,%1,%2,%3}, {%4,%5,%6,%7}, {%8,%9}, {%0,%1,%2,%3};"
        : "+f"(c[0]), "+f"(c[1]), "+f"(c[2]), "+f"(c[3])
        : "r"(a0), "r"(a1), "r"(a2), "r"(a3), "r"(b0), "r"(b1));
}

// ---------------------------------------------------------------------------
// Fused preprocessing (one launch): 6 weight transposes + x convert.
// scale for Wq/Wk includes sqrt(log2(e)) so scores land in log2 domain.
// ---------------------------------------------------------------------------
__device__ __forceinline__ void transpose_tile(
    const float* __restrict__ src, __half* __restrict__ dst,
    int R, int C, float scale, int bx, int by)
{
    __shared__ float t[32][33];
    const int tx = threadIdx.x, ty = threadIdx.y;
#pragma unroll
    for (int j = 0; j < 4; j++)
        t[ty + 8 * j][tx] = src[(size_t)(by * 32 + ty + 8 * j) * C + bx * 32 + tx];
    __syncthreads();
#pragma unroll
    for (int j = 0; j < 4; j++)
        dst[(size_t)(bx * 32 + ty + 8 * j) * R + by * 32 + tx] =
            __float2half_rn(t[tx][ty + 8 * j] * scale);
}

__global__ __launch_bounds__(256)
void prep_all(const float* __restrict__ x,  const float* __restrict__ Wq,
              const float* __restrict__ Wk, const float* __restrict__ Wv,
              const float* __restrict__ Wo, const float* __restrict__ W1,
              const float* __restrict__ W2, float scale)
{
    const int gb = blockIdx.x;
    if (gb < 256) {
        transpose_tile(Wq, g_wqkvT,             Dv, Dv, scale, gb & 15, gb >> 4);
    } else if (gb < 512) {
        int t = gb - 256;
        transpose_tile(Wk, g_wqkvT + 512 * Dv,  Dv, Dv, scale, t & 15, t >> 4);
    } else if (gb < 768) {
        int t = gb - 512;
        transpose_tile(Wv, g_wqkvT + 1024 * Dv, Dv, Dv, 1.0f, t & 15, t >> 4);
    } else if (gb < 1024) {
        int t = gb - 768;
        transpose_tile(Wo, g_woT, Dv, Dv, 1.0f, t & 15, t >> 4);
    } else if (gb < 2048) {
        int t = gb - 1024;                      // W1: R=512, C=2048, grid 64x16
        transpose_tile(W1, g_w1T, Dv, DEv, 1.0f, t & 63, t >> 6);
    } else if (gb < 3072) {
        int t = gb - 2048;                      // W2: R=2048, C=512, grid 16x64
        transpose_tile(W2, g_w2T, DEv, Dv, 1.0f, t & 15, t >> 4);
    } else {
        int t = gb - 3072;
        int tid = threadIdx.y * 32 + threadIdx.x;
        int i = t * 256 + tid;
        for (int idx = i; idx < Mv * Dv / 4; idx += 256 * 256) {
            float4 v = *(const float4*)(x + 4 * idx);
            __half2 h0 = __floats2half2_rn(v.x, v.y);
            __half2 h1 = __floats2half2_rn(v.z, v.w);
            *(__half2*)(g_xh + 4 * idx)     = h0;
            *(__half2*)(g_xh + 4 * idx + 2) = h1;
        }
    }
}

// ---------------------------------------------------------------------------
// fp16 GEMM: BK=64 slabs, 3-stage cp.async ring (2 in flight), ldmatrix,
// m16n8k16. A: [M,K] half; BT: [N,K] half; CTA 128x128, 256 thr, 4Mx2N warps.
// Stage: A[128][72] + B[128][72] halfs (144B rows, ldmatrix conflict-free).
// EP_QKV: q|k -> Ch (stride 1024), V -> Vt via SMEM transpose (coalesced).
// EP_RES: Ch = A@B + res(fp32).  EP_BIAS_RES: Cf = A@B + bias + aux(half).
// ---------------------------------------------------------------------------
#define GHS 72
#define STG_HALFS (2 * 128 * GHS)                // 18432
#define GEMM_SMEM (3 * STG_HALFS * 2)            // 110592 B

template <int EPI>
__global__ __launch_bounds__(256, 2)
void gemm_mma(const __half* __restrict__ A, const __half* __restrict__ BT,
              const float* __restrict__ bias, const float* __restrict__ res,
              float* __restrict__ Cf, __half* __restrict__ Ch,
              __half* __restrict__ aux, int M, int N, int K)
{
    extern __shared__ __half smh[];

    const int tid = threadIdx.x;
    const int wid = tid >> 5;
    const int lid = tid & 31;
    const int gid = lid >> 2;
    const int tq  = lid & 3;
    const int wm  = (wid >> 1) * 32;
    const int wn  = (wid & 1) * 64;
    const int bm  = blockIdx.y * 128;
    const int bn  = blockIdx.x * 128;
    const int NS  = K >> 6;

    const int lrow = (lid & 7) + ((lid >> 3) & 1) * 8;
    const int ak16 = lid >> 4;
    const int brow = lid & 7;
    const int bk16 = (lid >> 3) & 1;
    const int bn8  = (lid >> 4) & 1;

    auto issue = [&](int s, int buf) {
        __half* ab = smh + buf * STG_HALFS;
        __half* bb = ab + 128 * GHS;
        const __half* Ap = A  + (size_t)bm * K + s * 64;
        const __half* Bp = BT + (size_t)bn * K + s * 64;
#pragma unroll
        for (int it = 0; it < 4; it++) {
            int idx = it * 256 + tid;
            int r = idx >> 3, c = (idx & 7) * 8;
            CP_ASYNC16(smem_u32(ab + r * GHS + c), Ap + (size_t)r * K + c);
        }
#pragma unroll
        for (int it = 0; it < 4; it++) {
            int idx = it * 256 + tid;
            int r = idx >> 3, c = (idx & 7) * 8;
            CP_ASYNC16(smem_u32(bb + r * GHS + c), Bp + (size_t)r * K + c);
        }
        CP_COMMIT();
    };

    float acc[2][8][4];
#pragma unroll
    for (int mt = 0; mt < 2; mt++)
#pragma unroll
        for (int nt = 0; nt < 8; nt++)
#pragma unroll
            for (int u = 0; u < 4; u++) acc[mt][nt][u] = 0.0f;

    issue(0, 0);
    issue(1, 1);

    for (int s = 0; s < NS; s++) {
        if (s == NS - 1) { CP_WAIT(0); } else { CP_WAIT(1); }
        __syncthreads();
        if (s + 2 < NS) issue(s + 2, (s + 2) % 3);

        const uint32_t stage = smem_u32(smh + (s % 3) * STG_HALFS);
        const uint32_t a_base = stage + ((wm + lrow) * GHS) * 2 + ak16 * 16;
        const uint32_t b_base = stage + 128 * GHS * 2
                              + ((wn + bn8 * 8 + brow) * GHS) * 2 + bk16 * 16;
#pragma unroll
        for (int ks = 0; ks < 4; ks++) {
            uint32_t a[2][4];
#pragma unroll
            for (int mt = 0; mt < 2; mt++)
                LDSM_X4(a[mt][0], a[mt][1], a[mt][2], a[mt][3],
                        a_base + mt * (16 * GHS * 2) + ks * 32);
#pragma unroll
            for (int p = 0; p < 4; p++) {
                uint32_t b0, b1, b2, b3;
                LDSM_X4(b0, b1, b2, b3, b_base + p * (16 * GHS * 2) + ks * 32);
#pragma unroll
                for (int mt = 0; mt < 2; mt++) {
                    mma_f16(acc[mt][2 * p],     a[mt][0], a[mt][1], a[mt][2], a[mt][3], b0, b1);
                    mma_f16(acc[mt][2 * p + 1], a[mt][0], a[mt][1], a[mt][2], a[mt][3], b2, b3);
                }
            }
        }
    }

    // ---- Epilogue ----
    if (EPI == EP_QKV && bn >= 1024) {
        // V block: transpose through SMEM for coalesced Vt writes.
        __syncthreads();                       // mainloop smem now free
        __half* tile = smh;                    // [128 n][136 m] halfs
#pragma unroll
        for (int mt = 0; mt < 2; mt++) {
#pragma unroll
            for (int half_ = 0; half_ < 2; half_++) {
                const int mLoc = wm + mt * 16 + gid + half_ * 8;
#pragma unroll
                for (int nt = 0; nt < 8; nt++) {
                    const int nLoc = wn + nt * 8 + 2 * tq;
                    tile[nLoc * 136 + mLoc] =
                        __float2half_rn(acc[mt][nt][half_ * 2 + 0]);
                    tile[(nLoc + 1) * 136 + mLoc] =
                        __float2half_rn(acc[mt][nt][half_ * 2 + 1]);
                }
            }
        }
        __syncthreads();
        // Copy out: thread t -> row n = t>>1, 64 halfs starting at (t&1)*64.
        {
            const int n = tid >> 1;
            const int mc = (tid & 1) * 64;
            const uint4* src = (const uint4*)(tile + n * 136 + mc);
            uint4* dst = (uint4*)(aux + (size_t)(bn - 1024 + n) * Mv + bm + mc);
#pragma unroll
            for (int j = 0; j < 8; j++) dst[j] = src[j];
        }
        return;
    }

#pragma unroll
    for (int mt = 0; mt < 2; mt++) {
#pragma unroll
        for (int half_ = 0; half_ < 2; half_++) {
            const int row = bm + wm + mt * 16 + gid + half_ * 8;
#pragma unroll
            for (int nt = 0; nt < 8; nt++) {
                const int col = bn + wn + nt * 8 + 2 * tq;
                float v0 = acc[mt][nt][half_ * 2 + 0];
                float v1 = acc[mt][nt][half_ * 2 + 1];
                if (EPI == EP_QKV) {
                    *(__half2*)(Ch + (size_t)row * 1024 + col) =
                        __floats2half2_rn(v0, v1);
                } else if (EPI == EP_RES) {
                    v0 += res[(size_t)row * N + col];
                    v1 += res[(size_t)row * N + col + 1];
                    *(__half2*)(Ch + (size_t)row * N + col) = __floats2half2_rn(v0, v1);
                } else if (EPI == EP_BIAS_GELU) {
                    v0 = gelu_tanh(v0 + bias[col]);
                    v1 = gelu_tanh(v1 + bias[col + 1]);
                    *(__half2*)(Ch + (size_t)row * N + col) = __floats2half2_rn(v0, v1);
                } else {   // EP_BIAS_RES: half residual from aux
                    __half2 r2 = *(const __half2*)(aux + (size_t)row * N + col);
                    float2 rf = __half22float2(r2);
                    v0 += bias[col]     + rf.x;
                    v1 += bias[col + 1] + rf.y;
                    *(float2*)(Cf + (size_t)row * N + col) = make_float2(v0, v1);
                }
            }
        }
    }
}

// ---------------------------------------------------------------------------
// fp16 flash attention (unchanged from round 13/14): 128 q-rows/CTA, 256 thr,
// 2 CTA/SM, 4-stage cp.async ring, h2exp2 softmax, register P-fragments.
// ---------------------------------------------------------------------------
#define ATTN_SMEM ((4 * 9216 + 9216) * 2)   // 92160 B
#define NT_TILES (Sv / 64)                  // 32

__global__ __launch_bounds__(256, 2)
void attn_mma(const __half* __restrict__ qk, const __half* __restrict__ vt,
              __half* __restrict__ o)
{
    extern __shared__ __half smh[];
    __half* Qs = smh + 36864;

    const int tid = threadIdx.x;
    const int wid = tid >> 5;
    const int lid = tid & 31;
    const int gid = lid >> 2;
    const int tq  = lid & 3;
    const int qt  = blockIdx.x;
    const int h   = blockIdx.y;
    const int b   = blockIdx.z;

    const int lrow = (lid & 7) + ((lid >> 3) & 1) * 8;
    const int ak16 = lid >> 4;
    const int brow = lid & 7;
    const int bk16 = (lid >> 3) & 1;
    const int bn8  = (lid >> 4) & 1;

    const __half* qb  = qk + ((size_t)b * Sv + qt * 128) * 1024 + h * HDv;
    const __half* kb  = qk + (size_t)b * Sv * 1024 + 512 + h * HDv;
    const __half* vtb = vt + (size_t)(h * HDv) * Mv + b * Sv;

    auto issue_tile = [&](int kt, int buf) {
#pragma unroll
        for (int it = 0; it < 2; it++) {       // K: [key][72]
            int idx = it * 256 + tid;
            int key = idx >> 3, ch = (idx & 7) * 8;
            CP_ASYNC16(smem_u32(smh + buf * 9216 + key * 72 + ch),
                       kb + (size_t)(kt * 64 + key) * 1024 + ch);
        }
#pragma unroll
        for (int it = 0; it < 2; it++) {       // V: [d][72]
            int idx = it * 256 + tid;
            int d = idx >> 3, ch = (idx & 7) * 8;
            CP_ASYNC16(smem_u32(smh + buf * 9216 + 4608 + d * 72 + ch),
                       vtb + (size_t)d * Mv + kt * 64 + ch);
        }
        CP_COMMIT();
    };

    issue_tile(0, 0);

#pragma unroll
    for (int it = 0; it < 4; it++) {
        int idx = it * 256 + tid;
        int r = idx >> 3, c = (idx & 7) * 8;
        CP_ASYNC16(smem_u32(Qs + r * 72 + c), qb + (size_t)r * 1024 + c);
    }
    CP_COMMIT();
    issue_tile(1, 1);
    issue_tile(2, 2);

    CP_WAIT(2);
    __syncthreads();

    uint32_t qf[4][4];
    {
        const uint32_t qaddr = smem_u32(Qs) + ((wid * 16 + lrow) * 72) * 2 + ak16 * 16;
#pragma unroll
        for (int ks = 0; ks < 4; ks++)
            LDSM_X4(qf[ks][0], qf[ks][1], qf[ks][2], qf[ks][3], qaddr + ks * 32);
    }

    float oacc[8][4];
#pragma unroll
    for (int dt = 0; dt < 8; dt++)
#pragma unroll
        for (int u = 0; u < 4; u++) oacc[dt][u] = 0.0f;
    float mrow0 = -1e30f, mrow1 = -1e30f, lrow0 = 0.0f, lrow1 = 0.0f;

    for (int kt = 0; kt < NT_TILES; kt++) {
        const int buf = kt & 3;
        const int rem = NT_TILES - 1 - kt;
        if (rem >= 2)      { CP_WAIT(2); }
        else if (rem == 1) { CP_WAIT(1); }
        else               { CP_WAIT(0); }
        __syncthreads();
        if (kt + 3 < NT_TILES) issue_tile(kt + 3, (kt + 3) & 3);

        const uint32_t kaddr = smem_u32(smh + buf * 9216)
                             + ((bn8 * 8 + brow) * 72) * 2 + bk16 * 16;
        const uint32_t vaddr = smem_u32(smh + buf * 9216 + 4608)
                             + ((bn8 * 8 + brow) * 72) * 2 + bk16 * 16;

        float sacc[8][4];
#pragma unroll
        for (int nt = 0; nt < 8; nt++)
#pragma unroll
            for (int u = 0; u < 4; u++) sacc[nt][u] = 0.0f;
#pragma unroll
        for (int ks = 0; ks < 4; ks++) {
#pragma unroll
            for (int p = 0; p < 4; p++) {
                uint32_t b0, b1, b2, b3;
                LDSM_X4(b0, b1, b2, b3, kaddr + p * (16 * 72 * 2) + ks * 32);
                mma_f16(sacc[2 * p],     qf[ks][0], qf[ks][1], qf[ks][2], qf[ks][3], b0, b1);
                mma_f16(sacc[2 * p + 1], qf[ks][0], qf[ks][1], qf[ks][2], qf[ks][3], b2, b3);
            }
        }

        float mx0 = -1e30f, mx1 = -1e30f;
#pragma unroll
        for (int nt = 0; nt < 8; nt++) {
            mx0 = fmaxf(mx0, fmaxf(sacc[nt][0], sacc[nt][1]));
            mx1 = fmaxf(mx1, fmaxf(sacc[nt][2], sacc[nt][3]));
        }
        mx0 = fmaxf(mx0, __shfl_xor_sync(0xffffffffu, mx0, 1));
        mx0 = fmaxf(mx0, __shfl_xor_sync(0xffffffffu, mx0, 2));
        mx1 = fmaxf(mx1, __shfl_xor_sync(0xffffffffu, mx1, 1));
        mx1 = fmaxf(mx1, __shfl_xor_sync(0xffffffffu, mx1, 2));
        float mn0 = fmaxf(mrow0, mx0), mn1 = fmaxf(mrow1, mx1);
        float corr0 = exp2f(mrow0 - mn0), corr1 = exp2f(mrow1 - mn1);

        uint32_t pf[8], pg[8];
        float ps0 = 0.0f, ps1 = 0.0f;
#pragma unroll
        for (int nt = 0; nt < 8; nt++) {
            __half2 e0 = h2exp2(__floats2half2_rn(sacc[nt][0] - mn0, sacc[nt][1] - mn0));
            __half2 e1 = h2exp2(__floats2half2_rn(sacc[nt][2] - mn1, sacc[nt][3] - mn1));
            pf[nt] = *reinterpret_cast<uint32_t*>(&e0);
            pg[nt] = *reinterpret_cast<uint32_t*>(&e1);
            float2 f0 = __half22float2(e0);
            float2 f1 = __half22float2(e1);
            ps0 += f0.x + f0.y;
            ps1 += f1.x + f1.y;
        }
        ps0 += __shfl_xor_sync(0xffffffffu, ps0, 1);
        ps0 += __shfl_xor_sync(0xffffffffu, ps0, 2);
        ps1 += __shfl_xor_sync(0xffffffffu, ps1, 1);
        ps1 += __shfl_xor_sync(0xffffffffu, ps1, 2);
        lrow0 = lrow0 * corr0 + ps0;
        lrow1 = lrow1 * corr1 + ps1;
        mrow0 = mn0; mrow1 = mn1;
#pragma unroll
        for (int dt = 0; dt < 8; dt++) {
            oacc[dt][0] *= corr0; oacc[dt][1] *= corr0;
            oacc[dt][2] *= corr1; oacc[dt][3] *= corr1;
        }

#pragma unroll
        for (int ks = 0; ks < 4; ks++) {
            uint32_t pa0 = pf[2 * ks],     pa1 = pg[2 * ks];
            uint32_t pa2 = pf[2 * ks + 1], pa3 = pg[2 * ks + 1];
#pragma unroll
            for (int p = 0; p < 4; p++) {
                uint32_t b0, b1, b2, b3;
                LDSM_X4(b0, b1, b2, b3, vaddr + p * (16 * 72 * 2) + ks * 32);
                mma_f16(oacc[2 * p],     pa0, pa1, pa2, pa3, b0, b1);
                mma_f16(oacc[2 * p + 1], pa0, pa1, pa2, pa3, b2, b3);
            }
        }
    }

    float inv0 = 1.0f / lrow0, inv1 = 1.0f / lrow1;
    __half* ob = o + ((size_t)b * Sv + qt * 128 + wid * 16) * Dv + h * HDv;
#pragma unroll
    for (int dt = 0; dt < 8; dt++) {
        int col = dt * 8 + 2 * tq;
        *(__half2*)(ob + (size_t)gid * Dv + col) =
            __floats2half2_rn(oacc[dt][0] * inv0, oacc[dt][1] * inv0);
        *(__half2*)(ob + (size_t)(gid + 8) * Dv + col) =
            __floats2half2_rn(oacc[dt][2] * inv1, oacc[dt][3] * inv1);
    }
}

// ---------------------------------------------------------------------------
// Launch
// ---------------------------------------------------------------------------
extern "C" void kernel_launch(void* const* d_in, const int* in_sizes, int n_in,
                              void* d_out, int out_size)
{
    const float* x  = (const float*)d_in[0];
    const float* Wq = (const float*)d_in[1];
    const float* Wk = (const float*)d_in[2];
    const float* Wv = (const float*)d_in[3];
    const float* Wo = (const float*)d_in[4];
    const float* W1 = (const float*)d_in[5];
    const float* b1 = (const float*)d_in[6];
    const float* W2 = (const float*)d_in[7];
    const float* b2 = (const float*)d_in[8];
    float* out = (float*)d_out;

    __half *xh, *wqkvT, *woT, *w1T, *w2T, *qk, *vt, *oh, *x1h, *hh;
    cudaGetSymbolAddress((void**)&xh,    g_xh);
    cudaGetSymbolAddress((void**)&wqkvT, g_wqkvT);
    cudaGetSymbolAddress((void**)&woT,   g_woT);
    cudaGetSymbolAddress((void**)&w1T,   g_w1T);
    cudaGetSymbolAddress((void**)&w2T,   g_w2T);
    cudaGetSymbolAddress((void**)&qk,    g_qk);
    cudaGetSymbolAddress((void**)&vt,    g_vt);
    cudaGetSymbolAddress((void**)&oh,    g_oh);
    cudaGetSymbolAddress((void**)&x1h,   g_x1h);
    cudaGetSymbolAddress((void**)&hh,    g_hh);

    cudaFuncSetAttribute(gemm_mma<EP_QKV>,       cudaFuncAttributeMaxDynamicSharedMemorySize, GEMM_SMEM);
    cudaFuncSetAttribute(gemm_mma<EP_RES>,       cudaFuncAttributeMaxDynamicSharedMemorySize, GEMM_SMEM);
    cudaFuncSetAttribute(gemm_mma<EP_BIAS_GELU>, cudaFuncAttributeMaxDynamicSharedMemorySize, GEMM_SMEM);
    cudaFuncSetAttribute(gemm_mma<EP_BIAS_RES>,  cudaFuncAttributeMaxDynamicSharedMemorySize, GEMM_SMEM);
    cudaFuncSetAttribute(attn_mma, cudaFuncAttributeMaxDynamicSharedMemorySize, ATTN_SMEM);

    // 512^(-0.25) * sqrt(log2(e)) -> scores come out of QK^T in log2 domain
    const float scale = 0.21022410381342865f * 1.2011224087864498f;
    dim3 blk(256);

    prep_all<<<3328, dim3(32, 8)>>>(x, Wq, Wk, Wv, Wo, W1, W2, scale);

    // qkv projections: q|k -> g_qk, v -> g_vt (SMEM-transposed, coalesced)
    gemm_mma<EP_QKV><<<dim3(QKVN / 128, Mv / 128), blk, GEMM_SMEM>>>(
        xh, wqkvT, nullptr, nullptr, nullptr, qk, vt, Mv, QKVN, Dv);

    attn_mma<<<dim3(Sv / 128, Hv, Bv), blk, ATTN_SMEM>>>(qk, vt, oh);

    // x1 = o @ Wo + x   (half only)
    gemm_mma<EP_RES><<<dim3(Dv / 128, Mv / 128), blk, GEMM_SMEM>>>(
        oh, woT, nullptr, x, nullptr, x1h, nullptr, Mv, Dv, Dv);
    // h = gelu(x1 @ W1 + b1)
    gemm_mma<EP_BIAS_GELU><<<dim3(DEv / 128, Mv / 128), blk, GEMM_SMEM>>>(
        x1h, w1T, b1, nullptr, nullptr, hh, nullptr, Mv, DEv, Dv);
    // out = h @ W2 + b2 + x1 (half residual)
    gemm_mma<EP_BIAS_RES><<<dim3(Dv / 128, Mv / 128), blk, GEMM_SMEM>>>(
        hh, w2T, b2, nullptr, out, nullptr, x1h, Mv, Dv, DEv);
}